// round 8
// baseline (speedup 1.0000x reference)
#include <cuda_runtime.h>
#include <cuda_fp16.h>
#include <cstdint>
#include <math.h>

#define DIM_IN 2048
#define QDIM   2048
#define LATENT 1024
#define N_ROIS 4096
#define N_BANK 8192
#define LN_EPS 1e-5f

// ============================ static scratch ====================================
__device__ __half g_feat_h[(size_t)N_ROIS * QDIM];
__device__ __half g_feat_l[(size_t)N_ROIS * QDIM];
__device__ __half g_kb_h[(size_t)N_BANK * DIM_IN];
__device__ __half g_kb_l[(size_t)N_BANK * DIM_IN];
#define WSZ ((size_t)LATENT * QDIM)
__device__ __half g_W_h[7 * WSZ];
__device__ __half g_W_l[7 * WSZ];
__device__ __half g_Q_h[(size_t)2 * N_ROIS * LATENT];
__device__ __half g_Q_l[(size_t)2 * N_ROIS * LATENT];
__device__ __half g_K_h[(size_t)2 * N_BANK * LATENT];
__device__ __half g_Vt_h[(size_t)2 * LATENT * N_BANK];
__device__ float  g_S  [(size_t)2 * N_ROIS * N_BANK];
__device__ __half g_E_h[(size_t)2 * N_ROIS * N_BANK];
__device__ __half g_E_l[(size_t)2 * N_ROIS * N_BANK];
__device__ float  g_F  [(size_t)2 * N_ROIS * LATENT];
__device__ __half g_X_h[(size_t)N_ROIS * LATENT];
__device__ __half g_X_l[(size_t)N_ROIS * LATENT];
__device__ float g_rsum[2 * N_ROIS];

// ============================ PTX helpers =======================================
__device__ __forceinline__ uint32_t smem_u32(const void* p) {
    uint32_t a;
    asm("{ .reg .u64 t; cvta.to.shared.u64 t, %1; cvt.u32.u64 %0, t; }" : "=r"(a) : "l"(p));
    return a;
}
__device__ __forceinline__ void cp_async16(uint32_t s, const void* g) {
    asm volatile("cp.async.cg.shared.global [%0], [%1], 16;\n" :: "r"(s), "l"(g));
}
#define CP_COMMIT() asm volatile("cp.async.commit_group;\n" ::: "memory")
#define CP_WAIT1()  asm volatile("cp.async.wait_group 1;\n" ::: "memory")

#define LDSM_X4(r, a)                                                               \
    asm volatile("ldmatrix.sync.aligned.m8n8.x4.shared.b16 {%0,%1,%2,%3}, [%4];"    \
        : "=r"((r)[0]), "=r"((r)[1]), "=r"((r)[2]), "=r"((r)[3]) : "r"(a))

// fp32-accum HMMA (main term)
#define MMA_F16(c, a, b0, b1)                                                       \
    asm volatile("mma.sync.aligned.m16n8k16.row.col.f32.f16.f16.f32 "               \
        "{%0,%1,%2,%3}, {%4,%5,%6,%7}, {%8,%9}, {%0,%1,%2,%3};"                     \
        : "+f"((c)[0]), "+f"((c)[1]), "+f"((c)[2]), "+f"((c)[3])                    \
        : "r"((a)[0]), "r"((a)[1]), "r"((a)[2]), "r"((a)[3]), "r"(b0), "r"(b1))

// fp16-accum HMMA (correction terms)
#define MMA_F16A(c, a, b0, b1)                                                      \
    asm volatile("mma.sync.aligned.m16n8k16.row.col.f16.f16.f16.f16 "               \
        "{%0,%1}, {%2,%3,%4,%5}, {%6,%7}, {%0,%1};"                                 \
        : "+r"((c)[0]), "+r"((c)[1])                                                \
        : "r"((a)[0]), "r"((a)[1]), "r"((a)[2]), "r"((a)[3]), "r"(b0), "r"(b1))

__device__ __forceinline__ void split16(float x, __half& h, __half& l) {
    h = __float2half_rn(x);
    l = __float2half_rn(x - __half2float(h));
}

// ============================ tiled split-fp16 MMA GEMM =========================
// C = A * B^T. Main term hiA*hiB in fp32 accum; corrections in fp16 accum:
// T2=true : + loA*hiB          (A split, B hi only)
// T2=false: + loA*hiB + hiA*loB (both split; FFN)
// MODE 0: fp16 split out (+col-bias) | 1: fp16 split out (+row-bias)
// MODE 2: f32 *alpha | 3: f32 *1/rsum[row] | 4: f32 +col-bias ; SLO: store lo.
// Block 128x256x32, 8 warps, warp 64x64, 3-stage cp.async.
#define A_TILE_B 10240
#define B_TILE_B 20480

template<bool T2>
__device__ __forceinline__ void load_stage_g(uint32_t st,
    const __half* __restrict__ Ah, const __half* __restrict__ Al, int lda, int m0,
    const __half* __restrict__ Bh, const __half* __restrict__ Bl, int ldb, int n0,
    int k0, int tid)
{
#pragma unroll
    for (int it = 0; it < 2; ++it) {
        int id = tid + it * 256;
        int r  = id >> 2;
        int cw = id & 3;
        uint32_t soff = (uint32_t)(r * 80 + cw * 16);
        size_t ga = (size_t)(m0 + r) * lda + k0 + cw * 8;
        cp_async16(st +            soff, Ah + ga);
        cp_async16(st + A_TILE_B + soff, Al + ga);
    }
#pragma unroll
    for (int it = 0; it < 4; ++it) {
        int id = tid + it * 256;
        int r  = id >> 2;
        int cw = id & 3;
        uint32_t soff = (uint32_t)(r * 80 + cw * 16);
        size_t gb = (size_t)(n0 + r) * ldb + k0 + cw * 8;
        cp_async16(st + 2 * A_TILE_B + soff, Bh + gb);
        if (!T2) cp_async16(st + 2 * A_TILE_B + B_TILE_B + soff, Bl + gb);
    }
}

template<int MODE, bool T2, bool SLO>
__global__ __launch_bounds__(256, 1)
void gemm_f16(const __half* __restrict__ Ah, const __half* __restrict__ Al, int lda,
              const __half* __restrict__ Bh, const __half* __restrict__ Bl, int ldb,
              int K,
              float* __restrict__ Cf,
              __half* __restrict__ Ch, __half* __restrict__ Cl, int ldc,
              float alpha, const float* __restrict__ bias, const float* __restrict__ rsum)
{
    constexpr uint32_t STAGE_B = T2 ? (2 * A_TILE_B + B_TILE_B)
                                    : (2 * A_TILE_B + 2 * B_TILE_B);
    extern __shared__ __align__(16) char smem[];
    const uint32_t sbase = smem_u32(smem);
    const int tid = threadIdx.x, wid = tid >> 5, lane = tid & 31;
    const int m0 = blockIdx.y * 128, n0 = blockIdx.x * 256;
    const int wm = wid & 1;            // 0..1  (M, 64 rows)
    const int wn = wid >> 1;           // 0..3  (N, 64 cols)

    const uint32_t aoff = (uint32_t)((wm * 64 + (lane & 15)) * 80 + (lane >> 4) * 16);
    const uint32_t boff = (uint32_t)((wn * 64 + ((lane >> 4) & 1) * 8 + (lane & 7)) * 80
                                     + ((lane >> 3) & 1) * 16);

    float    accf[4][4][8];
    uint32_t acch[4][4][4];
#pragma unroll
    for (int i = 0; i < 4; i++)
#pragma unroll
        for (int j = 0; j < 4; j++) {
#pragma unroll
            for (int q = 0; q < 8; q++) accf[i][j][q] = 0.f;
#pragma unroll
            for (int q = 0; q < 4; q++) acch[i][j][q] = 0u;
        }

    const int nc = K >> 5;

    load_stage_g<T2>(sbase, Ah, Al, lda, m0, Bh, Bl, ldb, n0, 0, tid);
    CP_COMMIT();
    if (nc > 1) load_stage_g<T2>(sbase + STAGE_B, Ah, Al, lda, m0, Bh, Bl, ldb, n0, 32, tid);
    CP_COMMIT();

#pragma unroll 1
    for (int c = 0; c < nc; c++) {
        CP_WAIT1();
        __syncthreads();
        int cn = c + 2;
        if (cn < nc)
            load_stage_g<T2>(sbase + (uint32_t)(cn % 3) * STAGE_B, Ah, Al, lda, m0, Bh, Bl, ldb, n0, cn * 32, tid);
        CP_COMMIT();

        const uint32_t st  = sbase + (uint32_t)(c % 3) * STAGE_B;
        const uint32_t sAh = st, sAl = st + A_TILE_B;
        const uint32_t sBh = st + 2 * A_TILE_B;
        const uint32_t sBl = st + 2 * A_TILE_B + B_TILE_B;
#pragma unroll
        for (int ks = 0; ks < 2; ks++) {
            uint32_t ah[4][4], al[4][4];
#pragma unroll
            for (int mi = 0; mi < 4; mi++) {
                uint32_t off = aoff + (uint32_t)(mi * 1280 + ks * 32);
                LDSM_X4(ah[mi], sAh + off);
                LDSM_X4(al[mi], sAl + off);
            }
#pragma unroll
            for (int p = 0; p < 4; p++) {
                uint32_t off = boff + (uint32_t)(p * 1280 + ks * 32);
                uint32_t bh[4];
                LDSM_X4(bh, sBh + off);
                if (T2) {
#pragma unroll
                    for (int mi = 0; mi < 4; mi++) {
                        MMA_F16((accf[mi][p] + 0), ah[mi], bh[0], bh[1]);
                        MMA_F16((accf[mi][p] + 4), ah[mi], bh[2], bh[3]);
                        MMA_F16A((acch[mi][p] + 0), al[mi], bh[0], bh[1]);
                        MMA_F16A((acch[mi][p] + 2), al[mi], bh[2], bh[3]);
                    }
                } else {
                    uint32_t bl[4];
                    LDSM_X4(bl, sBl + off);
#pragma unroll
                    for (int mi = 0; mi < 4; mi++) {
                        MMA_F16((accf[mi][p] + 0), ah[mi], bh[0], bh[1]);
                        MMA_F16((accf[mi][p] + 4), ah[mi], bh[2], bh[3]);
                        MMA_F16A((acch[mi][p] + 0), al[mi], bh[0], bh[1]);
                        MMA_F16A((acch[mi][p] + 2), al[mi], bh[2], bh[3]);
                        MMA_F16A((acch[mi][p] + 0), ah[mi], bl[0], bl[1]);
                        MMA_F16A((acch[mi][p] + 2), ah[mi], bl[2], bl[3]);
                    }
                }
            }
        }
    }

    // ---- epilogue
#pragma unroll
    for (int mi = 0; mi < 4; mi++) {
        const int r0 = m0 + wm * 64 + mi * 16 + (lane >> 2);
        const int r1 = r0 + 8;
        float s0 = 1.f, s1 = 1.f, rb0 = 0.f, rb1 = 0.f;
        if (MODE == 3) { s0 = 1.f / rsum[r0]; s1 = 1.f / rsum[r1]; }
        if (MODE == 1) { rb0 = bias[r0]; rb1 = bias[r1]; }
#pragma unroll
        for (int p = 0; p < 4; p++) {
#pragma unroll
            for (int n8 = 0; n8 < 2; n8++) {
                const int col = n0 + wn * 64 + p * 16 + n8 * 8 + 2 * (lane & 3);
                const float* a4 = accf[mi][p] + n8 * 4;
                __half2 c0 = *reinterpret_cast<const __half2*>(&acch[mi][p][n8 * 2 + 0]);
                __half2 c1 = *reinterpret_cast<const __half2*>(&acch[mi][p][n8 * 2 + 1]);
                float v0 = a4[0] + __low2float(c0), v1 = a4[1] + __high2float(c0);
                float v2 = a4[2] + __low2float(c1), v3 = a4[3] + __high2float(c1);
                if (MODE == 2) { v0 *= alpha; v1 *= alpha; v2 *= alpha; v3 *= alpha; }
                if (MODE == 3) { v0 *= s0; v1 *= s0; v2 *= s1; v3 *= s1; }
                if (MODE == 0 || MODE == 4) {
                    float b0 = bias[col], b1 = bias[col + 1];
                    v0 += b0; v1 += b1; v2 += b0; v3 += b1;
                }
                if (MODE == 1) { v0 += rb0; v1 += rb0; v2 += rb1; v3 += rb1; }

                if (MODE == 2 || MODE == 3 || MODE == 4) {
                    *reinterpret_cast<float2*>(Cf + (size_t)r0 * ldc + col) = make_float2(v0, v1);
                    *reinterpret_cast<float2*>(Cf + (size_t)r1 * ldc + col) = make_float2(v2, v3);
                } else {
                    __half h0, h1, h2, h3, l0, l1, l2, l3;
                    split16(v0, h0, l0); split16(v1, h1, l1);
                    split16(v2, h2, l2); split16(v3, h3, l3);
                    *reinterpret_cast<__half2*>(Ch + (size_t)r0 * ldc + col) = __halves2half2(h0, h1);
                    *reinterpret_cast<__half2*>(Ch + (size_t)r1 * ldc + col) = __halves2half2(h2, h3);
                    if (SLO) {
                        *reinterpret_cast<__half2*>(Cl + (size_t)r0 * ldc + col) = __halves2half2(l0, l1);
                        *reinterpret_cast<__half2*>(Cl + (size_t)r1 * ldc + col) = __halves2half2(l2, l3);
                    }
                }
            }
        }
    }
}

// ============================ aux kernels =======================================
__global__ __launch_bounds__(256)
void split4_kernel(const float4* __restrict__ s, __half2* __restrict__ h,
                   __half2* __restrict__ l, int n4)
{
    for (int i = blockIdx.x * blockDim.x + threadIdx.x; i < n4; i += gridDim.x * blockDim.x) {
        float4 v = s[i];
        __half hx, hy, hz, hw, lx, ly, lz, lw;
        split16(v.x, hx, lx); split16(v.y, hy, ly);
        split16(v.z, hz, lz); split16(v.w, hw, lw);
        h[2 * i + 0] = __halves2half2(hx, hy);
        h[2 * i + 1] = __halves2half2(hz, hw);
        l[2 * i + 0] = __halves2half2(lx, ly);
        l[2 * i + 1] = __halves2half2(lz, lw);
    }
}

__global__ __launch_bounds__(256)
void softmax_row_kernel(const float* __restrict__ S,
                        __half2* __restrict__ Eh, __half2* __restrict__ El,
                        float* __restrict__ rsum)
{
    __shared__ __align__(16) float srow[N_BANK];
    __shared__ float redm[8], reds[8], Msh;
    const int row = blockIdx.x;
    const float4* sg = reinterpret_cast<const float4*>(S + (size_t)row * N_BANK);
    float4* ss = reinterpret_cast<float4*>(srow);
    const int t = threadIdx.x, lane = t & 31, w = t >> 5;

    float m = -1e30f;
#pragma unroll
    for (int it = 0; it < 8; it++) {
        int i = t + it * 256;
        float4 v = sg[i];
        ss[i] = v;
        m = fmaxf(m, fmaxf(fmaxf(v.x, v.y), fmaxf(v.z, v.w)));
    }
#pragma unroll
    for (int off = 16; off > 0; off >>= 1) m = fmaxf(m, __shfl_xor_sync(0xffffffffu, m, off));
    if (lane == 0) redm[w] = m;
    __syncthreads();
    if (t == 0) {
        float mm = redm[0];
#pragma unroll
        for (int i = 1; i < 8; i++) mm = fmaxf(mm, redm[i]);
        Msh = mm;
    }
    __syncthreads();
    const float M = Msh;

    __half2* ehr = Eh + (size_t)row * (N_BANK / 2);
    __half2* elr = El + (size_t)row * (N_BANK / 2);
    float s = 0.f;
#pragma unroll
    for (int it = 0; it < 8; it++) {
        int i = t + it * 256;
        float4 v = ss[i];
        float e0 = __expf(v.x - M), e1 = __expf(v.y - M);
        float e2 = __expf(v.z - M), e3 = __expf(v.w - M);
        s += e0 + e1 + e2 + e3;
        __half h0, h1, h2, h3, l0, l1, l2, l3;
        split16(e0, h0, l0); split16(e1, h1, l1);
        split16(e2, h2, l2); split16(e3, h3, l3);
        ehr[2 * i + 0] = __halves2half2(h0, h1);
        ehr[2 * i + 1] = __halves2half2(h2, h3);
        elr[2 * i + 0] = __halves2half2(l0, l1);
        elr[2 * i + 1] = __halves2half2(l2, l3);
    }
#pragma unroll
    for (int off = 16; off > 0; off >>= 1) s += __shfl_xor_sync(0xffffffffu, s, off);
    if (lane == 0) reds[w] = s;
    __syncthreads();
    if (t == 0) {
        float ss2 = 0.f;
#pragma unroll
        for (int i = 0; i < 8; i++) ss2 += reds[i];
        rsum[row] = ss2;
    }
}

__global__ __launch_bounds__(256)
void gate_ln_kernel(const float* __restrict__ F,
                    const float* __restrict__ ln_w, const float* __restrict__ ln_b,
                    const float* __restrict__ prelu_a,
                    __half* __restrict__ Xh, __half* __restrict__ Xl)
{
    const int row = blockIdx.x;
    const int t = threadIdx.x, lane = t & 31, w = t >> 5;
    const float4 f1 = reinterpret_cast<const float4*>(F + (size_t)row * LATENT)[t];
    const float4 f2 = reinterpret_cast<const float4*>(F + (size_t)(N_ROIS + row) * LATENT)[t];
    float4 c;
    c.x = f1.x * f2.x; c.y = f1.y * f2.y; c.z = f1.z * f2.z; c.w = f1.w * f2.w;

    __shared__ float red[8], mu_sh, var_sh;
    float s = c.x + c.y + c.z + c.w;
#pragma unroll
    for (int off = 16; off > 0; off >>= 1) s += __shfl_xor_sync(0xffffffffu, s, off);
    if (lane == 0) red[w] = s;
    __syncthreads();
    if (t == 0) {
        float ss = 0.f;
#pragma unroll
        for (int i = 0; i < 8; i++) ss += red[i];
        mu_sh = ss * (1.f / LATENT);
    }
    __syncthreads();
    const float mu = mu_sh;
    float dx = c.x - mu, dy = c.y - mu, dz = c.z - mu, dw = c.w - mu;
    float sq = dx * dx + dy * dy + dz * dz + dw * dw;
#pragma unroll
    for (int off = 16; off > 0; off >>= 1) sq += __shfl_xor_sync(0xffffffffu, sq, off);
    __syncthreads();
    if (lane == 0) red[w] = sq;
    __syncthreads();
    if (t == 0) {
        float ss = 0.f;
#pragma unroll
        for (int i = 0; i < 8; i++) ss += red[i];
        var_sh = ss * (1.f / LATENT);
    }
    __syncthreads();
    const float inv = rsqrtf(var_sh + LN_EPS);
    const float slope = prelu_a[0];
    const float4 wv = reinterpret_cast<const float4*>(ln_w)[t];
    const float4 bv = reinterpret_cast<const float4*>(ln_b)[t];
    float4 x;
    x.x = dx * inv * wv.x + bv.x;  x.y = dy * inv * wv.y + bv.y;
    x.z = dz * inv * wv.z + bv.z;  x.w = dw * inv * wv.w + bv.w;
    x.x = x.x >= 0.f ? x.x : slope * x.x;
    x.y = x.y >= 0.f ? x.y : slope * x.y;
    x.z = x.z >= 0.f ? x.z : slope * x.z;
    x.w = x.w >= 0.f ? x.w : slope * x.w;

    __half h0, h1, h2, h3, l0, l1, l2, l3;
    split16(x.x, h0, l0); split16(x.y, h1, l1);
    split16(x.z, h2, l2); split16(x.w, h3, l3);
    __half2* hp = reinterpret_cast<__half2*>(Xh + (size_t)row * LATENT);
    __half2* lp = reinterpret_cast<__half2*>(Xl + (size_t)row * LATENT);
    hp[2 * t + 0] = __halves2half2(h0, h1);
    hp[2 * t + 1] = __halves2half2(h2, h3);
    lp[2 * t + 0] = __halves2half2(l0, l1);
    lp[2 * t + 1] = __halves2half2(l2, l3);
}

// ============================ launch ============================================
static float* symf(const void* s) { void* p; cudaGetSymbolAddress(&p, s); return (float*)p; }
static __half* symh(const void* s) { void* p; cudaGetSymbolAddress(&p, s); return (__half*)p; }

extern "C" void kernel_launch(void* const* d_in, const int* in_sizes, int n_in,
                              void* d_out, int out_size)
{
    const float* feat     = (const float*)d_in[0];
    const float* key_bank = (const float*)d_in[1];
    const float* Wc1 = (const float*)d_in[2];  const float* bc1 = (const float*)d_in[3];
    const float* Wc2 = (const float*)d_in[4];  const float* bc2 = (const float*)d_in[5];
    const float* Wc3 = (const float*)d_in[6];  const float* bc3 = (const float*)d_in[7];
    const float* Wd1 = (const float*)d_in[8];  const float* bd1 = (const float*)d_in[9];
    const float* Wd2 = (const float*)d_in[10]; const float* bd2 = (const float*)d_in[11];
    const float* Wd3 = (const float*)d_in[12]; const float* bd3 = (const float*)d_in[13];
    const float* ln_w = (const float*)d_in[14];
    const float* ln_b = (const float*)d_in[15];
    const float* prelu_a = (const float*)d_in[16];
    const float* Wffn = (const float*)d_in[17];
    const float* bffn = (const float*)d_in[18];
    float* out = (float*)d_out;

    __half *feat_h = symh(&g_feat_h), *feat_l = symh(&g_feat_l);
    __half *kb_h = symh(&g_kb_h), *kb_l = symh(&g_kb_l);
    __half *W_h = symh(&g_W_h), *W_l = symh(&g_W_l);
    __half *Q_h = symh(&g_Q_h), *Q_l = symh(&g_Q_l);
    __half *K_h = symh(&g_K_h);
    __half *Vt_h = symh(&g_Vt_h);
    __half *E_h = symh(&g_E_h), *E_l = symh(&g_E_l);
    __half *X_h = symh(&g_X_h), *X_l = symh(&g_X_l);
    float *S = symf(&g_S), *F = symf(&g_F), *RS = symf(&g_rsum);

    const int SM_T2 = 3 * (2 * A_TILE_B + B_TILE_B);        // 122880
    const int SM_T3 = 3 * (2 * A_TILE_B + 2 * B_TILE_B);    // 184320
    cudaFuncSetAttribute(gemm_f16<0,true,true>,   cudaFuncAttributeMaxDynamicSharedMemorySize, SM_T2);
    cudaFuncSetAttribute(gemm_f16<0,true,false>,  cudaFuncAttributeMaxDynamicSharedMemorySize, SM_T2);
    cudaFuncSetAttribute(gemm_f16<1,true,false>,  cudaFuncAttributeMaxDynamicSharedMemorySize, SM_T2);
    cudaFuncSetAttribute(gemm_f16<2,true,false>,  cudaFuncAttributeMaxDynamicSharedMemorySize, SM_T2);
    cudaFuncSetAttribute(gemm_f16<3,true,false>,  cudaFuncAttributeMaxDynamicSharedMemorySize, SM_T2);
    cudaFuncSetAttribute(gemm_f16<4,false,false>, cudaFuncAttributeMaxDynamicSharedMemorySize, SM_T3);

    const dim3 blk(256);
    const int SG = 1184;

    // ---- split-convert inputs & weights (fp16 hi/lo)
    split4_kernel<<<SG, blk>>>((const float4*)feat, (__half2*)feat_h, (__half2*)feat_l, (int)((size_t)N_ROIS * QDIM / 4));
    split4_kernel<<<SG, blk>>>((const float4*)key_bank, (__half2*)kb_h, (__half2*)kb_l, (int)((size_t)N_BANK * DIM_IN / 4));
    const float* Ws[7] = { Wc1, Wd1, Wc2, Wd2, Wc3, Wd3, Wffn };
    for (int i = 0; i < 7; i++)
        split4_kernel<<<SG, blk>>>((const float4*)Ws[i],
            (__half2*)(W_h + i * WSZ), (__half2*)(W_l + i * WSZ), (int)(WSZ / 4));

    const size_t QO = (size_t)N_ROIS * LATENT;
    const size_t KO = (size_t)N_BANK * LATENT;
    const size_t VO = (size_t)LATENT * N_BANK;
    const size_t SO = (size_t)N_ROIS * N_BANK;

    // ---- Q projections (A=feat split, B=W hi) -> store hi+lo
    gemm_f16<0,true,true><<<dim3(4, 32), blk, SM_T2>>>(feat_h, feat_l, QDIM,
        W_h + 0 * WSZ, nullptr, QDIM, QDIM, nullptr, Q_h, Q_l, LATENT, 0.f, bc1, nullptr);
    gemm_f16<0,true,true><<<dim3(4, 32), blk, SM_T2>>>(feat_h, feat_l, QDIM,
        W_h + 1 * WSZ, nullptr, QDIM, QDIM, nullptr, Q_h + QO, Q_l + QO, LATENT, 0.f, bd1, nullptr);
    // ---- K projections -> hi only
    gemm_f16<0,true,false><<<dim3(4, 64), blk, SM_T2>>>(kb_h, kb_l, DIM_IN,
        W_h + 2 * WSZ, nullptr, DIM_IN, DIM_IN, nullptr, K_h, nullptr, LATENT, 0.f, bc2, nullptr);
    gemm_f16<0,true,false><<<dim3(4, 64), blk, SM_T2>>>(kb_h, kb_l, DIM_IN,
        W_h + 3 * WSZ, nullptr, DIM_IN, DIM_IN, nullptr, K_h + KO, nullptr, LATENT, 0.f, bd2, nullptr);
    // ---- Vt projections -> hi only, row bias
    gemm_f16<1,true,false><<<dim3(32, 8), blk, SM_T2>>>(W_h + 4 * WSZ, W_l + 4 * WSZ, DIM_IN,
        kb_h, nullptr, DIM_IN, DIM_IN, nullptr, Vt_h, nullptr, N_BANK, 0.f, bc3, nullptr);
    gemm_f16<1,true,false><<<dim3(32, 8), blk, SM_T2>>>(W_h + 5 * WSZ, W_l + 5 * WSZ, DIM_IN,
        kb_h, nullptr, DIM_IN, DIM_IN, nullptr, Vt_h + VO, nullptr, N_BANK, 0.f, bd3, nullptr);

    // ---- scores: S = (Q K^T)/32
    gemm_f16<2,true,false><<<dim3(32, 32), blk, SM_T2>>>(Q_h, Q_l, LATENT,
        K_h, nullptr, LATENT, LATENT, S, nullptr, nullptr, N_BANK, 0.03125f, nullptr, nullptr);
    gemm_f16<2,true,false><<<dim3(32, 32), blk, SM_T2>>>(Q_h + QO, Q_l + QO, LATENT,
        K_h + KO, nullptr, LATENT, LATENT, S + SO, nullptr, nullptr, N_BANK, 0.03125f, nullptr, nullptr);

    // ---- fused softmax (max + exp-split + sum)
    softmax_row_kernel<<<2 * N_ROIS, blk>>>(S, (__half2*)E_h, (__half2*)E_l, RS);

    // ---- PV: F = (E Vt^T)/rsum
    gemm_f16<3,true,false><<<dim3(4, 32), blk, SM_T2>>>(E_h, E_l, N_BANK,
        Vt_h, nullptr, N_BANK, N_BANK, F, nullptr, nullptr, LATENT, 0.f, nullptr, RS);
    gemm_f16<3,true,false><<<dim3(4, 32), blk, SM_T2>>>(E_h + SO, E_l + SO, N_BANK,
        Vt_h + VO, nullptr, N_BANK, N_BANK, F + QO, nullptr, nullptr, LATENT, 0.f, nullptr, RS + N_ROIS);

    // ---- gate + LN + PReLU -> X split
    gate_ln_kernel<<<N_ROIS, blk>>>(F, ln_w, ln_b, prelu_a, X_h, X_l);

    // ---- FFN (3-term)
    gemm_f16<4,false,false><<<dim3(8, 32), blk, SM_T3>>>(X_h, X_l, LATENT,
        W_h + 6 * WSZ, W_l + 6 * WSZ, LATENT, LATENT, out, nullptr, nullptr, DIM_IN, 0.f, bffn, nullptr);
}

// round 9
// speedup vs baseline: 1.3075x; 1.3075x over previous
#include <cuda_runtime.h>
#include <cuda_fp16.h>
#include <cstdint>
#include <math.h>

#define DIM_IN 2048
#define QDIM   2048
#define LATENT 1024
#define N_ROIS 4096
#define N_BANK 8192
#define LN_EPS 1e-5f

// ============================ static scratch ====================================
__device__ __half g_feat_h[(size_t)N_ROIS * QDIM];
__device__ __half g_feat_l[(size_t)N_ROIS * QDIM];
__device__ __half g_kb_h[(size_t)N_BANK * DIM_IN];
__device__ __half g_kb_l[(size_t)N_BANK * DIM_IN];
#define WSZ ((size_t)LATENT * QDIM)
__device__ __half g_W_h[7 * WSZ];
__device__ __half g_W_l[7 * WSZ];
__device__ __half g_Q_h[(size_t)2 * N_ROIS * LATENT];
__device__ __half g_K_h[(size_t)2 * N_BANK * LATENT];
__device__ __half g_Vt_h[(size_t)2 * LATENT * N_BANK];
__device__ float  g_S  [(size_t)2 * N_ROIS * N_BANK];
__device__ __half g_E_h[(size_t)2 * N_ROIS * N_BANK];
__device__ float  g_F  [(size_t)2 * N_ROIS * LATENT];
__device__ __half g_X_h[(size_t)N_ROIS * LATENT];
__device__ __half g_X_l[(size_t)N_ROIS * LATENT];
__device__ float g_rsum[2 * N_ROIS];

// ============================ PTX helpers =======================================
__device__ __forceinline__ uint32_t smem_u32(const void* p) {
    uint32_t a;
    asm("{ .reg .u64 t; cvta.to.shared.u64 t, %1; cvt.u32.u64 %0, t; }" : "=r"(a) : "l"(p));
    return a;
}
__device__ __forceinline__ void cp_async16(uint32_t s, const void* g) {
    asm volatile("cp.async.cg.shared.global [%0], [%1], 16;\n" :: "r"(s), "l"(g));
}
#define CP_COMMIT() asm volatile("cp.async.commit_group;\n" ::: "memory")
#define CP_WAIT1()  asm volatile("cp.async.wait_group 1;\n" ::: "memory")

#define LDSM_X4(r, a)                                                               \
    asm volatile("ldmatrix.sync.aligned.m8n8.x4.shared.b16 {%0,%1,%2,%3}, [%4];"    \
        : "=r"((r)[0]), "=r"((r)[1]), "=r"((r)[2]), "=r"((r)[3]) : "r"(a))

#define MMA_F16(c, a, b0, b1)                                                       \
    asm volatile("mma.sync.aligned.m16n8k16.row.col.f32.f16.f16.f32 "               \
        "{%0,%1,%2,%3}, {%4,%5,%6,%7}, {%8,%9}, {%0,%1,%2,%3};"                     \
        : "+f"((c)[0]), "+f"((c)[1]), "+f"((c)[2]), "+f"((c)[3])                    \
        : "r"((a)[0]), "r"((a)[1]), "r"((a)[2]), "r"((a)[3]), "r"(b0), "r"(b1))

__device__ __forceinline__ void split16(float x, __half& h, __half& l) {
    h = __float2half_rn(x);
    l = __float2half_rn(x - __half2float(h));
}

// ============================ tiled split-fp16 MMA GEMM =========================
// C = A * B^T, fp32 accum.
// TERMS=1: hiA*hiB                    (attention QK / PV)
// TERMS=2: + loA*hiB                  (projections)
// TERMS=3: + loA*hiB + hiA*loB       (FFN)
// MODE 0: fp16 out (+col-bias) | 1: fp16 out (+row-bias)
// MODE 2: f32 *alpha | 3: f32 *1/rsum[row] | 4: f32 +col-bias
// SLO: also store lo plane (MODE0/1).
// Block 128x256x32, 8 warps, warp 64x64, 3-stage cp.async.
#define A_TILE_B 10240
#define B_TILE_B 20480

template<int TERMS>
__device__ __forceinline__ void load_stage_g(uint32_t st,
    const __half* __restrict__ Ah, const __half* __restrict__ Al, int lda, int m0,
    const __half* __restrict__ Bh, const __half* __restrict__ Bl, int ldb, int n0,
    int k0, int tid)
{
    constexpr uint32_t B_OFF = (TERMS >= 2 ? 2u : 1u) * A_TILE_B;
#pragma unroll
    for (int it = 0; it < 2; ++it) {
        int id = tid + it * 256;
        int r  = id >> 2;
        int cw = id & 3;
        uint32_t soff = (uint32_t)(r * 80 + cw * 16);
        size_t ga = (size_t)(m0 + r) * lda + k0 + cw * 8;
        cp_async16(st + soff, Ah + ga);
        if (TERMS >= 2) cp_async16(st + A_TILE_B + soff, Al + ga);
    }
#pragma unroll
    for (int it = 0; it < 4; ++it) {
        int id = tid + it * 256;
        int r  = id >> 2;
        int cw = id & 3;
        uint32_t soff = (uint32_t)(r * 80 + cw * 16);
        size_t gb = (size_t)(n0 + r) * ldb + k0 + cw * 8;
        cp_async16(st + B_OFF + soff, Bh + gb);
        if (TERMS == 3) cp_async16(st + B_OFF + B_TILE_B + soff, Bl + gb);
    }
}

template<int MODE, int TERMS, bool SLO>
__global__ __launch_bounds__(256, 1)
void gemm_f16(const __half* __restrict__ Ah, const __half* __restrict__ Al, int lda,
              const __half* __restrict__ Bh, const __half* __restrict__ Bl, int ldb,
              int K,
              float* __restrict__ Cf,
              __half* __restrict__ Ch, __half* __restrict__ Cl, int ldc,
              float alpha, const float* __restrict__ bias, const float* __restrict__ rsum)
{
    constexpr uint32_t B_OFF   = (TERMS >= 2 ? 2u : 1u) * A_TILE_B;
    constexpr uint32_t STAGE_B = B_OFF + (TERMS == 3 ? 2u : 1u) * B_TILE_B;
    extern __shared__ __align__(16) char smem[];
    const uint32_t sbase = smem_u32(smem);
    const int tid = threadIdx.x, wid = tid >> 5, lane = tid & 31;
    const int m0 = blockIdx.y * 128, n0 = blockIdx.x * 256;
    const int wm = wid & 1;
    const int wn = wid >> 1;

    const uint32_t aoff = (uint32_t)((wm * 64 + (lane & 15)) * 80 + (lane >> 4) * 16);
    const uint32_t boff = (uint32_t)((wn * 64 + ((lane >> 4) & 1) * 8 + (lane & 7)) * 80
                                     + ((lane >> 3) & 1) * 16);

    float acc[4][4][8];
#pragma unroll
    for (int i = 0; i < 4; i++)
#pragma unroll
        for (int j = 0; j < 4; j++)
#pragma unroll
            for (int q = 0; q < 8; q++) acc[i][j][q] = 0.f;

    const int nc = K >> 5;

    load_stage_g<TERMS>(sbase, Ah, Al, lda, m0, Bh, Bl, ldb, n0, 0, tid);
    CP_COMMIT();
    if (nc > 1) load_stage_g<TERMS>(sbase + STAGE_B, Ah, Al, lda, m0, Bh, Bl, ldb, n0, 32, tid);
    CP_COMMIT();

#pragma unroll 1
    for (int c = 0; c < nc; c++) {
        CP_WAIT1();
        __syncthreads();
        int cn = c + 2;
        if (cn < nc)
            load_stage_g<TERMS>(sbase + (uint32_t)(cn % 3) * STAGE_B, Ah, Al, lda, m0, Bh, Bl, ldb, n0, cn * 32, tid);
        CP_COMMIT();

        const uint32_t st  = sbase + (uint32_t)(c % 3) * STAGE_B;
        const uint32_t sAh = st, sAl = st + A_TILE_B;
        const uint32_t sBh = st + B_OFF;
        const uint32_t sBl = st + B_OFF + B_TILE_B;
#pragma unroll
        for (int ks = 0; ks < 2; ks++) {
            uint32_t ah[4][4], al[4][4];
#pragma unroll
            for (int mi = 0; mi < 4; mi++) {
                uint32_t off = aoff + (uint32_t)(mi * 1280 + ks * 32);
                LDSM_X4(ah[mi], sAh + off);
                if (TERMS >= 2) LDSM_X4(al[mi], sAl + off);
            }
#pragma unroll
            for (int p = 0; p < 4; p++) {
                uint32_t off = boff + (uint32_t)(p * 1280 + ks * 32);
                uint32_t bh[4];
                LDSM_X4(bh, sBh + off);
                if (TERMS == 3) {
                    uint32_t bl[4];
                    LDSM_X4(bl, sBl + off);
#pragma unroll
                    for (int mi = 0; mi < 4; mi++) {
                        MMA_F16((acc[mi][p] + 0), ah[mi], bh[0], bh[1]);
                        MMA_F16((acc[mi][p] + 4), ah[mi], bh[2], bh[3]);
                        MMA_F16((acc[mi][p] + 0), ah[mi], bl[0], bl[1]);
                        MMA_F16((acc[mi][p] + 4), ah[mi], bl[2], bl[3]);
                        MMA_F16((acc[mi][p] + 0), al[mi], bh[0], bh[1]);
                        MMA_F16((acc[mi][p] + 4), al[mi], bh[2], bh[3]);
                    }
                } else if (TERMS == 2) {
#pragma unroll
                    for (int mi = 0; mi < 4; mi++) {
                        MMA_F16((acc[mi][p] + 0), ah[mi], bh[0], bh[1]);
                        MMA_F16((acc[mi][p] + 4), ah[mi], bh[2], bh[3]);
                        MMA_F16((acc[mi][p] + 0), al[mi], bh[0], bh[1]);
                        MMA_F16((acc[mi][p] + 4), al[mi], bh[2], bh[3]);
                    }
                } else {
#pragma unroll
                    for (int mi = 0; mi < 4; mi++) {
                        MMA_F16((acc[mi][p] + 0), ah[mi], bh[0], bh[1]);
                        MMA_F16((acc[mi][p] + 4), ah[mi], bh[2], bh[3]);
                    }
                }
            }
        }
    }

    // ---- epilogue
#pragma unroll
    for (int mi = 0; mi < 4; mi++) {
        const int r0 = m0 + wm * 64 + mi * 16 + (lane >> 2);
        const int r1 = r0 + 8;
        float s0 = 1.f, s1 = 1.f, rb0 = 0.f, rb1 = 0.f;
        if (MODE == 3) { s0 = 1.f / rsum[r0]; s1 = 1.f / rsum[r1]; }
        if (MODE == 1) { rb0 = bias[r0]; rb1 = bias[r1]; }
#pragma unroll
        for (int p = 0; p < 4; p++) {
#pragma unroll
            for (int n8 = 0; n8 < 2; n8++) {
                const int col = n0 + wn * 64 + p * 16 + n8 * 8 + 2 * (lane & 3);
                const float* a4 = acc[mi][p] + n8 * 4;
                float v0 = a4[0], v1 = a4[1], v2 = a4[2], v3 = a4[3];
                if (MODE == 2) { v0 *= alpha; v1 *= alpha; v2 *= alpha; v3 *= alpha; }
                if (MODE == 3) { v0 *= s0; v1 *= s0; v2 *= s1; v3 *= s1; }
                if (MODE == 0 || MODE == 4) {
                    float b0 = bias[col], b1 = bias[col + 1];
                    v0 += b0; v1 += b1; v2 += b0; v3 += b1;
                }
                if (MODE == 1) { v0 += rb0; v1 += rb0; v2 += rb1; v3 += rb1; }

                if (MODE == 2 || MODE == 3 || MODE == 4) {
                    *reinterpret_cast<float2*>(Cf + (size_t)r0 * ldc + col) = make_float2(v0, v1);
                    *reinterpret_cast<float2*>(Cf + (size_t)r1 * ldc + col) = make_float2(v2, v3);
                } else {
                    __half h0, h1, h2, h3, l0, l1, l2, l3;
                    split16(v0, h0, l0); split16(v1, h1, l1);
                    split16(v2, h2, l2); split16(v3, h3, l3);
                    *reinterpret_cast<__half2*>(Ch + (size_t)r0 * ldc + col) = __halves2half2(h0, h1);
                    *reinterpret_cast<__half2*>(Ch + (size_t)r1 * ldc + col) = __halves2half2(h2, h3);
                    if (SLO) {
                        *reinterpret_cast<__half2*>(Cl + (size_t)r0 * ldc + col) = __halves2half2(l0, l1);
                        *reinterpret_cast<__half2*>(Cl + (size_t)r1 * ldc + col) = __halves2half2(l2, l3);
                    }
                }
            }
        }
    }
}

// ============================ aux kernels =======================================
__global__ __launch_bounds__(256)
void split4_kernel(const float4* __restrict__ s, __half2* __restrict__ h,
                   __half2* __restrict__ l, int n4)
{
    for (int i = blockIdx.x * blockDim.x + threadIdx.x; i < n4; i += gridDim.x * blockDim.x) {
        float4 v = s[i];
        __half hx, hy, hz, hw, lx, ly, lz, lw;
        split16(v.x, hx, lx); split16(v.y, hy, ly);
        split16(v.z, hz, lz); split16(v.w, hw, lw);
        h[2 * i + 0] = __halves2half2(hx, hy);
        h[2 * i + 1] = __halves2half2(hz, hw);
        l[2 * i + 0] = __halves2half2(lx, ly);
        l[2 * i + 1] = __halves2half2(lz, lw);
    }
}

// fused: per-row max + exp (fp16 hi only) + sum; S row cached in smem.
__global__ __launch_bounds__(256)
void softmax_row_kernel(const float* __restrict__ S,
                        __half2* __restrict__ Eh, float* __restrict__ rsum)
{
    __shared__ __align__(16) float srow[N_BANK];
    __shared__ float redm[8], reds[8], Msh;
    const int row = blockIdx.x;
    const float4* sg = reinterpret_cast<const float4*>(S + (size_t)row * N_BANK);
    float4* ss = reinterpret_cast<float4*>(srow);
    const int t = threadIdx.x, lane = t & 31, w = t >> 5;

    float m = -1e30f;
#pragma unroll
    for (int it = 0; it < 8; it++) {
        int i = t + it * 256;
        float4 v = sg[i];
        ss[i] = v;
        m = fmaxf(m, fmaxf(fmaxf(v.x, v.y), fmaxf(v.z, v.w)));
    }
#pragma unroll
    for (int off = 16; off > 0; off >>= 1) m = fmaxf(m, __shfl_xor_sync(0xffffffffu, m, off));
    if (lane == 0) redm[w] = m;
    __syncthreads();
    if (t == 0) {
        float mm = redm[0];
#pragma unroll
        for (int i = 1; i < 8; i++) mm = fmaxf(mm, redm[i]);
        Msh = mm;
    }
    __syncthreads();
    const float M = Msh;

    __half2* ehr = Eh + (size_t)row * (N_BANK / 2);
    float s = 0.f;
#pragma unroll
    for (int it = 0; it < 8; it++) {
        int i = t + it * 256;
        float4 v = ss[i];
        float e0 = __expf(v.x - M), e1 = __expf(v.y - M);
        float e2 = __expf(v.z - M), e3 = __expf(v.w - M);
        s += e0 + e1 + e2 + e3;
        ehr[2 * i + 0] = __halves2half2(__float2half_rn(e0), __float2half_rn(e1));
        ehr[2 * i + 1] = __halves2half2(__float2half_rn(e2), __float2half_rn(e3));
    }
#pragma unroll
    for (int off = 16; off > 0; off >>= 1) s += __shfl_xor_sync(0xffffffffu, s, off);
    if (lane == 0) reds[w] = s;
    __syncthreads();
    if (t == 0) {
        float ss2 = 0.f;
#pragma unroll
        for (int i = 0; i < 8; i++) ss2 += reds[i];
        rsum[row] = ss2;
    }
}

__global__ __launch_bounds__(256)
void gate_ln_kernel(const float* __restrict__ F,
                    const float* __restrict__ ln_w, const float* __restrict__ ln_b,
                    const float* __restrict__ prelu_a,
                    __half* __restrict__ Xh, __half* __restrict__ Xl)
{
    const int row = blockIdx.x;
    const int t = threadIdx.x, lane = t & 31, w = t >> 5;
    const float4 f1 = reinterpret_cast<const float4*>(F + (size_t)row * LATENT)[t];
    const float4 f2 = reinterpret_cast<const float4*>(F + (size_t)(N_ROIS + row) * LATENT)[t];
    float4 c;
    c.x = f1.x * f2.x; c.y = f1.y * f2.y; c.z = f1.z * f2.z; c.w = f1.w * f2.w;

    __shared__ float red[8], mu_sh, var_sh;
    float s = c.x + c.y + c.z + c.w;
#pragma unroll
    for (int off = 16; off > 0; off >>= 1) s += __shfl_xor_sync(0xffffffffu, s, off);
    if (lane == 0) red[w] = s;
    __syncthreads();
    if (t == 0) {
        float ss = 0.f;
#pragma unroll
        for (int i = 0; i < 8; i++) ss += red[i];
        mu_sh = ss * (1.f / LATENT);
    }
    __syncthreads();
    const float mu = mu_sh;
    float dx = c.x - mu, dy = c.y - mu, dz = c.z - mu, dw = c.w - mu;
    float sq = dx * dx + dy * dy + dz * dz + dw * dw;
#pragma unroll
    for (int off = 16; off > 0; off >>= 1) sq += __shfl_xor_sync(0xffffffffu, sq, off);
    __syncthreads();
    if (lane == 0) red[w] = sq;
    __syncthreads();
    if (t == 0) {
        float ss = 0.f;
#pragma unroll
        for (int i = 0; i < 8; i++) ss += red[i];
        var_sh = ss * (1.f / LATENT);
    }
    __syncthreads();
    const float inv = rsqrtf(var_sh + LN_EPS);
    const float slope = prelu_a[0];
    const float4 wv = reinterpret_cast<const float4*>(ln_w)[t];
    const float4 bv = reinterpret_cast<const float4*>(ln_b)[t];
    float4 x;
    x.x = dx * inv * wv.x + bv.x;  x.y = dy * inv * wv.y + bv.y;
    x.z = dz * inv * wv.z + bv.z;  x.w = dw * inv * wv.w + bv.w;
    x.x = x.x >= 0.f ? x.x : slope * x.x;
    x.y = x.y >= 0.f ? x.y : slope * x.y;
    x.z = x.z >= 0.f ? x.z : slope * x.z;
    x.w = x.w >= 0.f ? x.w : slope * x.w;

    __half h0, h1, h2, h3, l0, l1, l2, l3;
    split16(x.x, h0, l0); split16(x.y, h1, l1);
    split16(x.z, h2, l2); split16(x.w, h3, l3);
    __half2* hp = reinterpret_cast<__half2*>(Xh + (size_t)row * LATENT);
    __half2* lp = reinterpret_cast<__half2*>(Xl + (size_t)row * LATENT);
    hp[2 * t + 0] = __halves2half2(h0, h1);
    hp[2 * t + 1] = __halves2half2(h2, h3);
    lp[2 * t + 0] = __halves2half2(l0, l1);
    lp[2 * t + 1] = __halves2half2(l2, l3);
}

// ============================ launch ============================================
static float* symf(const void* s) { void* p; cudaGetSymbolAddress(&p, s); return (float*)p; }
static __half* symh(const void* s) { void* p; cudaGetSymbolAddress(&p, s); return (__half*)p; }

extern "C" void kernel_launch(void* const* d_in, const int* in_sizes, int n_in,
                              void* d_out, int out_size)
{
    const float* feat     = (const float*)d_in[0];
    const float* key_bank = (const float*)d_in[1];
    const float* Wc1 = (const float*)d_in[2];  const float* bc1 = (const float*)d_in[3];
    const float* Wc2 = (const float*)d_in[4];  const float* bc2 = (const float*)d_in[5];
    const float* Wc3 = (const float*)d_in[6];  const float* bc3 = (const float*)d_in[7];
    const float* Wd1 = (const float*)d_in[8];  const float* bd1 = (const float*)d_in[9];
    const float* Wd2 = (const float*)d_in[10]; const float* bd2 = (const float*)d_in[11];
    const float* Wd3 = (const float*)d_in[12]; const float* bd3 = (const float*)d_in[13];
    const float* ln_w = (const float*)d_in[14];
    const float* ln_b = (const float*)d_in[15];
    const float* prelu_a = (const float*)d_in[16];
    const float* Wffn = (const float*)d_in[17];
    const float* bffn = (const float*)d_in[18];
    float* out = (float*)d_out;

    __half *feat_h = symh(&g_feat_h), *feat_l = symh(&g_feat_l);
    __half *kb_h = symh(&g_kb_h), *kb_l = symh(&g_kb_l);
    __half *W_h = symh(&g_W_h), *W_l = symh(&g_W_l);
    __half *Q_h = symh(&g_Q_h);
    __half *K_h = symh(&g_K_h);
    __half *Vt_h = symh(&g_Vt_h);
    __half *E_h = symh(&g_E_h);
    __half *X_h = symh(&g_X_h), *X_l = symh(&g_X_l);
    float *S = symf(&g_S), *F = symf(&g_F), *RS = symf(&g_rsum);

    const int SM_T1 = 3 * (A_TILE_B + B_TILE_B);            // 92160
    const int SM_T2 = 3 * (2 * A_TILE_B + B_TILE_B);        // 122880
    const int SM_T3 = 3 * (2 * A_TILE_B + 2 * B_TILE_B);    // 184320
    cudaFuncSetAttribute(gemm_f16<0,2,false>, cudaFuncAttributeMaxDynamicSharedMemorySize, SM_T2);
    cudaFuncSetAttribute(gemm_f16<1,2,false>, cudaFuncAttributeMaxDynamicSharedMemorySize, SM_T2);
    cudaFuncSetAttribute(gemm_f16<2,1,false>, cudaFuncAttributeMaxDynamicSharedMemorySize, SM_T1);
    cudaFuncSetAttribute(gemm_f16<3,1,false>, cudaFuncAttributeMaxDynamicSharedMemorySize, SM_T1);
    cudaFuncSetAttribute(gemm_f16<4,3,false>, cudaFuncAttributeMaxDynamicSharedMemorySize, SM_T3);

    const dim3 blk(256);
    const int SG = 1184;

    // ---- split-convert inputs & weights (fp16 hi/lo)
    split4_kernel<<<SG, blk>>>((const float4*)feat, (__half2*)feat_h, (__half2*)feat_l, (int)((size_t)N_ROIS * QDIM / 4));
    split4_kernel<<<SG, blk>>>((const float4*)key_bank, (__half2*)kb_h, (__half2*)kb_l, (int)((size_t)N_BANK * DIM_IN / 4));
    const float* Ws[7] = { Wc1, Wd1, Wc2, Wd2, Wc3, Wd3, Wffn };
    for (int i = 0; i < 7; i++)
        split4_kernel<<<SG, blk>>>((const float4*)Ws[i],
            (__half2*)(W_h + i * WSZ), (__half2*)(W_l + i * WSZ), (int)(WSZ / 4));

    const size_t QO = (size_t)N_ROIS * LATENT;
    const size_t KO = (size_t)N_BANK * LATENT;
    const size_t VO = (size_t)LATENT * N_BANK;
    const size_t SO = (size_t)N_ROIS * N_BANK;

    // ---- Q projections (2-term; hi out only)
    gemm_f16<0,2,false><<<dim3(4, 32), blk, SM_T2>>>(feat_h, feat_l, QDIM,
        W_h + 0 * WSZ, nullptr, QDIM, QDIM, nullptr, Q_h, nullptr, LATENT, 0.f, bc1, nullptr);
    gemm_f16<0,2,false><<<dim3(4, 32), blk, SM_T2>>>(feat_h, feat_l, QDIM,
        W_h + 1 * WSZ, nullptr, QDIM, QDIM, nullptr, Q_h + QO, nullptr, LATENT, 0.f, bd1, nullptr);
    // ---- K projections (2-term)
    gemm_f16<0,2,false><<<dim3(4, 64), blk, SM_T2>>>(kb_h, kb_l, DIM_IN,
        W_h + 2 * WSZ, nullptr, DIM_IN, DIM_IN, nullptr, K_h, nullptr, LATENT, 0.f, bc2, nullptr);
    gemm_f16<0,2,false><<<dim3(4, 64), blk, SM_T2>>>(kb_h, kb_l, DIM_IN,
        W_h + 3 * WSZ, nullptr, DIM_IN, DIM_IN, nullptr, K_h + KO, nullptr, LATENT, 0.f, bd2, nullptr);
    // ---- Vt projections (2-term, row bias)
    gemm_f16<1,2,false><<<dim3(32, 8), blk, SM_T2>>>(W_h + 4 * WSZ, W_l + 4 * WSZ, DIM_IN,
        kb_h, nullptr, DIM_IN, DIM_IN, nullptr, Vt_h, nullptr, N_BANK, 0.f, bc3, nullptr);
    gemm_f16<1,2,false><<<dim3(32, 8), blk, SM_T2>>>(W_h + 5 * WSZ, W_l + 5 * WSZ, DIM_IN,
        kb_h, nullptr, DIM_IN, DIM_IN, nullptr, Vt_h + VO, nullptr, N_BANK, 0.f, bd3, nullptr);

    // ---- scores: S = (Q K^T)/32   (1-term)
    gemm_f16<2,1,false><<<dim3(32, 32), blk, SM_T1>>>(Q_h, nullptr, LATENT,
        K_h, nullptr, LATENT, LATENT, S, nullptr, nullptr, N_BANK, 0.03125f, nullptr, nullptr);
    gemm_f16<2,1,false><<<dim3(32, 32), blk, SM_T1>>>(Q_h + QO, nullptr, LATENT,
        K_h + KO, nullptr, LATENT, LATENT, S + SO, nullptr, nullptr, N_BANK, 0.03125f, nullptr, nullptr);

    // ---- fused softmax (max + exp fp16 + sum)
    softmax_row_kernel<<<2 * N_ROIS, blk>>>(S, (__half2*)E_h, RS);

    // ---- PV: F = (E Vt^T)/rsum   (1-term)
    gemm_f16<3,1,false><<<dim3(4, 32), blk, SM_T1>>>(E_h, nullptr, N_BANK,
        Vt_h, nullptr, N_BANK, N_BANK, F, nullptr, nullptr, LATENT, 0.f, nullptr, RS);
    gemm_f16<3,1,false><<<dim3(4, 32), blk, SM_T1>>>(E_h + SO, nullptr, N_BANK,
        Vt_h + VO, nullptr, N_BANK, N_BANK, F + QO, nullptr, nullptr, LATENT, 0.f, nullptr, RS + N_ROIS);

    // ---- gate + LN + PReLU -> X split
    gate_ln_kernel<<<N_ROIS, blk>>>(F, ln_w, ln_b, prelu_a, X_h, X_l);

    // ---- FFN (3-term)
    gemm_f16<4,3,false><<<dim3(8, 32), blk, SM_T3>>>(X_h, X_l, LATENT,
        W_h + 6 * WSZ, W_l + 6 * WSZ, LATENT, LATENT, out, nullptr, nullptr, DIM_IN, 0.f, bffn, nullptr);
}

// round 10
// speedup vs baseline: 1.3703x; 1.0480x over previous
#include <cuda_runtime.h>
#include <cuda_fp16.h>
#include <cstdint>
#include <math.h>

#define DIM_IN 2048
#define QDIM   2048
#define LATENT 1024
#define N_ROIS 4096
#define N_BANK 8192
#define LN_EPS 1e-5f

// ============================ static scratch ====================================
__device__ __half g_feat_h[(size_t)N_ROIS * QDIM];
__device__ __half g_feat_l[(size_t)N_ROIS * QDIM];
__device__ __half g_kb_h[(size_t)N_BANK * DIM_IN];
__device__ __half g_kb_l[(size_t)N_BANK * DIM_IN];
#define WSZ ((size_t)LATENT * QDIM)
__device__ __half g_W_h[7 * WSZ];
__device__ __half g_W_l[7 * WSZ];
__device__ __half g_Q_h[(size_t)2 * N_ROIS * LATENT];
__device__ __half g_K_h[(size_t)2 * N_BANK * LATENT];
__device__ __half g_Vt_h[(size_t)2 * LATENT * N_BANK];
__device__ __half g_E_h[(size_t)2 * N_ROIS * N_BANK];
__device__ float  g_F  [(size_t)2 * N_ROIS * LATENT];
__device__ __half g_X_h[(size_t)N_ROIS * LATENT];
__device__ __half g_X_l[(size_t)N_ROIS * LATENT];
__device__ float g_rsum[2 * N_ROIS];

// ============================ PTX helpers =======================================
__device__ __forceinline__ uint32_t smem_u32(const void* p) {
    uint32_t a;
    asm("{ .reg .u64 t; cvta.to.shared.u64 t, %1; cvt.u32.u64 %0, t; }" : "=r"(a) : "l"(p));
    return a;
}
__device__ __forceinline__ void cp_async16(uint32_t s, const void* g) {
    asm volatile("cp.async.cg.shared.global [%0], [%1], 16;\n" :: "r"(s), "l"(g));
}
#define CP_COMMIT() asm volatile("cp.async.commit_group;\n" ::: "memory")
#define CP_WAIT1()  asm volatile("cp.async.wait_group 1;\n" ::: "memory")

#define LDSM_X4(r, a)                                                               \
    asm volatile("ldmatrix.sync.aligned.m8n8.x4.shared.b16 {%0,%1,%2,%3}, [%4];"    \
        : "=r"((r)[0]), "=r"((r)[1]), "=r"((r)[2]), "=r"((r)[3]) : "r"(a))

#define MMA_F16(c, a, b0, b1)                                                       \
    asm volatile("mma.sync.aligned.m16n8k16.row.col.f32.f16.f16.f32 "               \
        "{%0,%1,%2,%3}, {%4,%5,%6,%7}, {%8,%9}, {%0,%1,%2,%3};"                     \
        : "+f"((c)[0]), "+f"((c)[1]), "+f"((c)[2]), "+f"((c)[3])                    \
        : "r"((a)[0]), "r"((a)[1]), "r"((a)[2]), "r"((a)[3]), "r"(b0), "r"(b1))

__device__ __forceinline__ void split16(float x, __half& h, __half& l) {
    h = __float2half_rn(x);
    l = __float2half_rn(x - __half2float(h));
}

// ============================ tiled split-fp16 MMA GEMM =========================
// C = A * B^T, fp32 accum.
// TERMS=1: hiA*hiB | TERMS=2: + loA*hiB | TERMS=3: + loA*hiB + hiA*loB
// MODE 0: fp16 out (+col-bias) | 1: fp16 out (+row-bias)
// MODE 3: f32 *1/rsum[row] | 4: f32 +col-bias
// MODE 5: e = exp(alpha*acc) -> fp16 out; atomicAdd row sums into rsum
// Block 128x256x32, 8 warps, warp 64x64, 3-stage cp.async.
#define A_TILE_B 10240
#define B_TILE_B 20480

template<int TERMS>
__device__ __forceinline__ void load_stage_g(uint32_t st,
    const __half* __restrict__ Ah, const __half* __restrict__ Al, int lda, int m0,
    const __half* __restrict__ Bh, const __half* __restrict__ Bl, int ldb, int n0,
    int k0, int tid)
{
    constexpr uint32_t B_OFF = (TERMS >= 2 ? 2u : 1u) * A_TILE_B;
#pragma unroll
    for (int it = 0; it < 2; ++it) {
        int id = tid + it * 256;
        int r  = id >> 2;
        int cw = id & 3;
        uint32_t soff = (uint32_t)(r * 80 + cw * 16);
        size_t ga = (size_t)(m0 + r) * lda + k0 + cw * 8;
        cp_async16(st + soff, Ah + ga);
        if (TERMS >= 2) cp_async16(st + A_TILE_B + soff, Al + ga);
    }
#pragma unroll
    for (int it = 0; it < 4; ++it) {
        int id = tid + it * 256;
        int r  = id >> 2;
        int cw = id & 3;
        uint32_t soff = (uint32_t)(r * 80 + cw * 16);
        size_t gb = (size_t)(n0 + r) * ldb + k0 + cw * 8;
        cp_async16(st + B_OFF + soff, Bh + gb);
        if (TERMS == 3) cp_async16(st + B_OFF + B_TILE_B + soff, Bl + gb);
    }
}

template<int MODE, int TERMS, bool SLO>
__global__ __launch_bounds__(256, 1)
void gemm_f16(const __half* __restrict__ Ah, const __half* __restrict__ Al, int lda,
              const __half* __restrict__ Bh, const __half* __restrict__ Bl, int ldb,
              int K,
              float* __restrict__ Cf,
              __half* __restrict__ Ch, __half* __restrict__ Cl, int ldc,
              float alpha, const float* __restrict__ bias, float* __restrict__ rsum)
{
    constexpr uint32_t B_OFF   = (TERMS >= 2 ? 2u : 1u) * A_TILE_B;
    constexpr uint32_t STAGE_B = B_OFF + (TERMS == 3 ? 2u : 1u) * B_TILE_B;
    extern __shared__ __align__(16) char smem[];
    const uint32_t sbase = smem_u32(smem);
    const int tid = threadIdx.x, wid = tid >> 5, lane = tid & 31;
    const int m0 = blockIdx.y * 128, n0 = blockIdx.x * 256;
    const int wm = wid & 1;
    const int wn = wid >> 1;

    const uint32_t aoff = (uint32_t)((wm * 64 + (lane & 15)) * 80 + (lane >> 4) * 16);
    const uint32_t boff = (uint32_t)((wn * 64 + ((lane >> 4) & 1) * 8 + (lane & 7)) * 80
                                     + ((lane >> 3) & 1) * 16);

    float acc[4][4][8];
#pragma unroll
    for (int i = 0; i < 4; i++)
#pragma unroll
        for (int j = 0; j < 4; j++)
#pragma unroll
            for (int q = 0; q < 8; q++) acc[i][j][q] = 0.f;

    const int nc = K >> 5;

    load_stage_g<TERMS>(sbase, Ah, Al, lda, m0, Bh, Bl, ldb, n0, 0, tid);
    CP_COMMIT();
    if (nc > 1) load_stage_g<TERMS>(sbase + STAGE_B, Ah, Al, lda, m0, Bh, Bl, ldb, n0, 32, tid);
    CP_COMMIT();

#pragma unroll 1
    for (int c = 0; c < nc; c++) {
        CP_WAIT1();
        __syncthreads();
        int cn = c + 2;
        if (cn < nc)
            load_stage_g<TERMS>(sbase + (uint32_t)(cn % 3) * STAGE_B, Ah, Al, lda, m0, Bh, Bl, ldb, n0, cn * 32, tid);
        CP_COMMIT();

        const uint32_t st  = sbase + (uint32_t)(c % 3) * STAGE_B;
        const uint32_t sAh = st, sAl = st + A_TILE_B;
        const uint32_t sBh = st + B_OFF;
        const uint32_t sBl = st + B_OFF + B_TILE_B;
#pragma unroll
        for (int ks = 0; ks < 2; ks++) {
            uint32_t ah[4][4], al[4][4];
#pragma unroll
            for (int mi = 0; mi < 4; mi++) {
                uint32_t off = aoff + (uint32_t)(mi * 1280 + ks * 32);
                LDSM_X4(ah[mi], sAh + off);
                if (TERMS >= 2) LDSM_X4(al[mi], sAl + off);
            }
#pragma unroll
            for (int p = 0; p < 4; p++) {
                uint32_t off = boff + (uint32_t)(p * 1280 + ks * 32);
                uint32_t bh[4];
                LDSM_X4(bh, sBh + off);
                if (TERMS == 3) {
                    uint32_t bl[4];
                    LDSM_X4(bl, sBl + off);
#pragma unroll
                    for (int mi = 0; mi < 4; mi++) {
                        MMA_F16((acc[mi][p] + 0), ah[mi], bh[0], bh[1]);
                        MMA_F16((acc[mi][p] + 4), ah[mi], bh[2], bh[3]);
                        MMA_F16((acc[mi][p] + 0), ah[mi], bl[0], bl[1]);
                        MMA_F16((acc[mi][p] + 4), ah[mi], bl[2], bl[3]);
                        MMA_F16((acc[mi][p] + 0), al[mi], bh[0], bh[1]);
                        MMA_F16((acc[mi][p] + 4), al[mi], bh[2], bh[3]);
                    }
                } else if (TERMS == 2) {
#pragma unroll
                    for (int mi = 0; mi < 4; mi++) {
                        MMA_F16((acc[mi][p] + 0), ah[mi], bh[0], bh[1]);
                        MMA_F16((acc[mi][p] + 4), ah[mi], bh[2], bh[3]);
                        MMA_F16((acc[mi][p] + 0), al[mi], bh[0], bh[1]);
                        MMA_F16((acc[mi][p] + 4), al[mi], bh[2], bh[3]);
                    }
                } else {
#pragma unroll
                    for (int mi = 0; mi < 4; mi++) {
                        MMA_F16((acc[mi][p] + 0), ah[mi], bh[0], bh[1]);
                        MMA_F16((acc[mi][p] + 4), ah[mi], bh[2], bh[3]);
                    }
                }
            }
        }
    }

    // ---- epilogue
#pragma unroll
    for (int mi = 0; mi < 4; mi++) {
        const int r0 = m0 + wm * 64 + mi * 16 + (lane >> 2);
        const int r1 = r0 + 8;
        float s0 = 1.f, s1 = 1.f, rb0 = 0.f, rb1 = 0.f;
        if (MODE == 3) { s0 = 1.f / rsum[r0]; s1 = 1.f / rsum[r1]; }
        if (MODE == 1) { rb0 = bias[r0]; rb1 = bias[r1]; }
        float rsum0 = 0.f, rsum1 = 0.f;
#pragma unroll
        for (int p = 0; p < 4; p++) {
#pragma unroll
            for (int n8 = 0; n8 < 2; n8++) {
                const int col = n0 + wn * 64 + p * 16 + n8 * 8 + 2 * (lane & 3);
                const float* a4 = acc[mi][p] + n8 * 4;
                float v0 = a4[0], v1 = a4[1], v2 = a4[2], v3 = a4[3];
                if (MODE == 5) {
                    v0 = __expf(v0 * alpha); v1 = __expf(v1 * alpha);
                    v2 = __expf(v2 * alpha); v3 = __expf(v3 * alpha);
                    rsum0 += v0 + v1; rsum1 += v2 + v3;
                    *reinterpret_cast<__half2*>(Ch + (size_t)r0 * ldc + col) =
                        __halves2half2(__float2half_rn(v0), __float2half_rn(v1));
                    *reinterpret_cast<__half2*>(Ch + (size_t)r1 * ldc + col) =
                        __halves2half2(__float2half_rn(v2), __float2half_rn(v3));
                    continue;
                }
                if (MODE == 3) { v0 *= s0; v1 *= s0; v2 *= s1; v3 *= s1; }
                if (MODE == 0 || MODE == 4) {
                    float b0 = bias[col], b1 = bias[col + 1];
                    v0 += b0; v1 += b1; v2 += b0; v3 += b1;
                }
                if (MODE == 1) { v0 += rb0; v1 += rb0; v2 += rb1; v3 += rb1; }

                if (MODE == 3 || MODE == 4) {
                    *reinterpret_cast<float2*>(Cf + (size_t)r0 * ldc + col) = make_float2(v0, v1);
                    *reinterpret_cast<float2*>(Cf + (size_t)r1 * ldc + col) = make_float2(v2, v3);
                } else {
                    __half h0, h1, h2, h3, l0, l1, l2, l3;
                    split16(v0, h0, l0); split16(v1, h1, l1);
                    split16(v2, h2, l2); split16(v3, h3, l3);
                    *reinterpret_cast<__half2*>(Ch + (size_t)r0 * ldc + col) = __halves2half2(h0, h1);
                    *reinterpret_cast<__half2*>(Ch + (size_t)r1 * ldc + col) = __halves2half2(h2, h3);
                    if (SLO) {
                        *reinterpret_cast<__half2*>(Cl + (size_t)r0 * ldc + col) = __halves2half2(l0, l1);
                        *reinterpret_cast<__half2*>(Cl + (size_t)r1 * ldc + col) = __halves2half2(l2, l3);
                    }
                }
            }
        }
        if (MODE == 5) {
            // reduce partial sums across the 4 lanes sharing each row (lane bits 0-1)
            rsum0 += __shfl_xor_sync(0xffffffffu, rsum0, 1);
            rsum0 += __shfl_xor_sync(0xffffffffu, rsum0, 2);
            rsum1 += __shfl_xor_sync(0xffffffffu, rsum1, 1);
            rsum1 += __shfl_xor_sync(0xffffffffu, rsum1, 2);
            if ((lane & 3) == 0) {
                atomicAdd(rsum + r0, rsum0);
                atomicAdd(rsum + r1, rsum1);
            }
        }
    }
}

// ============================ aux kernels =======================================
__global__ __launch_bounds__(256)
void split4_kernel(const float4* __restrict__ s, __half2* __restrict__ h,
                   __half2* __restrict__ l, int n4)
{
    for (int i = blockIdx.x * blockDim.x + threadIdx.x; i < n4; i += gridDim.x * blockDim.x) {
        float4 v = s[i];
        __half hx, hy, hz, hw, lx, ly, lz, lw;
        split16(v.x, hx, lx); split16(v.y, hy, ly);
        split16(v.z, hz, lz); split16(v.w, hw, lw);
        h[2 * i + 0] = __halves2half2(hx, hy);
        h[2 * i + 1] = __halves2half2(hz, hw);
        l[2 * i + 0] = __halves2half2(lx, ly);
        l[2 * i + 1] = __halves2half2(lz, lw);
    }
}

__global__ __launch_bounds__(256)
void zero_kernel(float* __restrict__ p, int n)
{
    int i = blockIdx.x * blockDim.x + threadIdx.x;
    if (i < n) p[i] = 0.f;
}

__global__ __launch_bounds__(256)
void gate_ln_kernel(const float* __restrict__ F,
                    const float* __restrict__ ln_w, const float* __restrict__ ln_b,
                    const float* __restrict__ prelu_a,
                    __half* __restrict__ Xh, __half* __restrict__ Xl)
{
    const int row = blockIdx.x;
    const int t = threadIdx.x, lane = t & 31, w = t >> 5;
    const float4 f1 = reinterpret_cast<const float4*>(F + (size_t)row * LATENT)[t];
    const float4 f2 = reinterpret_cast<const float4*>(F + (size_t)(N_ROIS + row) * LATENT)[t];
    float4 c;
    c.x = f1.x * f2.x; c.y = f1.y * f2.y; c.z = f1.z * f2.z; c.w = f1.w * f2.w;

    __shared__ float red[8], mu_sh, var_sh;
    float s = c.x + c.y + c.z + c.w;
#pragma unroll
    for (int off = 16; off > 0; off >>= 1) s += __shfl_xor_sync(0xffffffffu, s, off);
    if (lane == 0) red[w] = s;
    __syncthreads();
    if (t == 0) {
        float ss = 0.f;
#pragma unroll
        for (int i = 0; i < 8; i++) ss += red[i];
        mu_sh = ss * (1.f / LATENT);
    }
    __syncthreads();
    const float mu = mu_sh;
    float dx = c.x - mu, dy = c.y - mu, dz = c.z - mu, dw = c.w - mu;
    float sq = dx * dx + dy * dy + dz * dz + dw * dw;
#pragma unroll
    for (int off = 16; off > 0; off >>= 1) sq += __shfl_xor_sync(0xffffffffu, sq, off);
    __syncthreads();
    if (lane == 0) red[w] = sq;
    __syncthreads();
    if (t == 0) {
        float ss = 0.f;
#pragma unroll
        for (int i = 0; i < 8; i++) ss += red[i];
        var_sh = ss * (1.f / LATENT);
    }
    __syncthreads();
    const float inv = rsqrtf(var_sh + LN_EPS);
    const float slope = prelu_a[0];
    const float4 wv = reinterpret_cast<const float4*>(ln_w)[t];
    const float4 bv = reinterpret_cast<const float4*>(ln_b)[t];
    float4 x;
    x.x = dx * inv * wv.x + bv.x;  x.y = dy * inv * wv.y + bv.y;
    x.z = dz * inv * wv.z + bv.z;  x.w = dw * inv * wv.w + bv.w;
    x.x = x.x >= 0.f ? x.x : slope * x.x;
    x.y = x.y >= 0.f ? x.y : slope * x.y;
    x.z = x.z >= 0.f ? x.z : slope * x.z;
    x.w = x.w >= 0.f ? x.w : slope * x.w;

    __half h0, h1, h2, h3, l0, l1, l2, l3;
    split16(x.x, h0, l0); split16(x.y, h1, l1);
    split16(x.z, h2, l2); split16(x.w, h3, l3);
    __half2* hp = reinterpret_cast<__half2*>(Xh + (size_t)row * LATENT);
    __half2* lp = reinterpret_cast<__half2*>(Xl + (size_t)row * LATENT);
    hp[2 * t + 0] = __halves2half2(h0, h1);
    hp[2 * t + 1] = __halves2half2(h2, h3);
    lp[2 * t + 0] = __halves2half2(l0, l1);
    lp[2 * t + 1] = __halves2half2(l2, l3);
}

// ============================ launch ============================================
static float* symf(const void* s) { void* p; cudaGetSymbolAddress(&p, s); return (float*)p; }
static __half* symh(const void* s) { void* p; cudaGetSymbolAddress(&p, s); return (__half*)p; }

extern "C" void kernel_launch(void* const* d_in, const int* in_sizes, int n_in,
                              void* d_out, int out_size)
{
    const float* feat     = (const float*)d_in[0];
    const float* key_bank = (const float*)d_in[1];
    const float* Wc1 = (const float*)d_in[2];  const float* bc1 = (const float*)d_in[3];
    const float* Wc2 = (const float*)d_in[4];  const float* bc2 = (const float*)d_in[5];
    const float* Wc3 = (const float*)d_in[6];  const float* bc3 = (const float*)d_in[7];
    const float* Wd1 = (const float*)d_in[8];  const float* bd1 = (const float*)d_in[9];
    const float* Wd2 = (const float*)d_in[10]; const float* bd2 = (const float*)d_in[11];
    const float* Wd3 = (const float*)d_in[12]; const float* bd3 = (const float*)d_in[13];
    const float* ln_w = (const float*)d_in[14];
    const float* ln_b = (const float*)d_in[15];
    const float* prelu_a = (const float*)d_in[16];
    const float* Wffn = (const float*)d_in[17];
    const float* bffn = (const float*)d_in[18];
    float* out = (float*)d_out;

    __half *feat_h = symh(&g_feat_h), *feat_l = symh(&g_feat_l);
    __half *kb_h = symh(&g_kb_h), *kb_l = symh(&g_kb_l);
    __half *W_h = symh(&g_W_h), *W_l = symh(&g_W_l);
    __half *Q_h = symh(&g_Q_h);
    __half *K_h = symh(&g_K_h);
    __half *Vt_h = symh(&g_Vt_h);
    __half *E_h = symh(&g_E_h);
    __half *X_h = symh(&g_X_h), *X_l = symh(&g_X_l);
    float *F = symf(&g_F), *RS = symf(&g_rsum);

    const int SM_T1 = 3 * (A_TILE_B + B_TILE_B);            // 92160
    const int SM_T2 = 3 * (2 * A_TILE_B + B_TILE_B);        // 122880
    cudaFuncSetAttribute(gemm_f16<0,2,false>, cudaFuncAttributeMaxDynamicSharedMemorySize, SM_T2);
    cudaFuncSetAttribute(gemm_f16<1,2,false>, cudaFuncAttributeMaxDynamicSharedMemorySize, SM_T2);
    cudaFuncSetAttribute(gemm_f16<5,1,false>, cudaFuncAttributeMaxDynamicSharedMemorySize, SM_T1);
    cudaFuncSetAttribute(gemm_f16<3,1,false>, cudaFuncAttributeMaxDynamicSharedMemorySize, SM_T1);
    cudaFuncSetAttribute(gemm_f16<4,2,false>, cudaFuncAttributeMaxDynamicSharedMemorySize, SM_T2);

    const dim3 blk(256);
    const int SG = 1184;

    // ---- split-convert inputs & weights (fp16 hi/lo)
    split4_kernel<<<SG, blk>>>((const float4*)feat, (__half2*)feat_h, (__half2*)feat_l, (int)((size_t)N_ROIS * QDIM / 4));
    split4_kernel<<<SG, blk>>>((const float4*)key_bank, (__half2*)kb_h, (__half2*)kb_l, (int)((size_t)N_BANK * DIM_IN / 4));
    const float* Ws[7] = { Wc1, Wd1, Wc2, Wd2, Wc3, Wd3, Wffn };
    for (int i = 0; i < 7; i++)
        split4_kernel<<<SG, blk>>>((const float4*)Ws[i],
            (__half2*)(W_h + i * WSZ), (__half2*)(W_l + i * WSZ), (int)(WSZ / 4));
    zero_kernel<<<(2 * N_ROIS + 255) / 256, blk>>>(RS, 2 * N_ROIS);

    const size_t QO = (size_t)N_ROIS * LATENT;
    const size_t KO = (size_t)N_BANK * LATENT;
    const size_t VO = (size_t)LATENT * N_BANK;
    const size_t SO = (size_t)N_ROIS * N_BANK;

    // ---- Q projections (2-term; hi out only)
    gemm_f16<0,2,false><<<dim3(4, 32), blk, SM_T2>>>(feat_h, feat_l, QDIM,
        W_h + 0 * WSZ, nullptr, QDIM, QDIM, nullptr, Q_h, nullptr, LATENT, 0.f, bc1, nullptr);
    gemm_f16<0,2,false><<<dim3(4, 32), blk, SM_T2>>>(feat_h, feat_l, QDIM,
        W_h + 1 * WSZ, nullptr, QDIM, QDIM, nullptr, Q_h + QO, nullptr, LATENT, 0.f, bd1, nullptr);
    // ---- K projections (2-term)
    gemm_f16<0,2,false><<<dim3(4, 64), blk, SM_T2>>>(kb_h, kb_l, DIM_IN,
        W_h + 2 * WSZ, nullptr, DIM_IN, DIM_IN, nullptr, K_h, nullptr, LATENT, 0.f, bc2, nullptr);
    gemm_f16<0,2,false><<<dim3(4, 64), blk, SM_T2>>>(kb_h, kb_l, DIM_IN,
        W_h + 3 * WSZ, nullptr, DIM_IN, DIM_IN, nullptr, K_h + KO, nullptr, LATENT, 0.f, bd2, nullptr);
    // ---- Vt projections (2-term, row bias)
    gemm_f16<1,2,false><<<dim3(32, 8), blk, SM_T2>>>(W_h + 4 * WSZ, W_l + 4 * WSZ, DIM_IN,
        kb_h, nullptr, DIM_IN, DIM_IN, nullptr, Vt_h, nullptr, N_BANK, 0.f, bc3, nullptr);
    gemm_f16<1,2,false><<<dim3(32, 8), blk, SM_T2>>>(W_h + 5 * WSZ, W_l + 5 * WSZ, DIM_IN,
        kb_h, nullptr, DIM_IN, DIM_IN, nullptr, Vt_h + VO, nullptr, N_BANK, 0.f, bd3, nullptr);

    // ---- scores + exp fused: E = exp((Q K^T)/32), rsum += row sums  (1-term)
    gemm_f16<5,1,false><<<dim3(32, 32), blk, SM_T1>>>(Q_h, nullptr, LATENT,
        K_h, nullptr, LATENT, LATENT, nullptr, E_h, nullptr, N_BANK, 0.03125f, nullptr, RS);
    gemm_f16<5,1,false><<<dim3(32, 32), blk, SM_T1>>>(Q_h + QO, nullptr, LATENT,
        K_h + KO, nullptr, LATENT, LATENT, nullptr, E_h + SO, nullptr, N_BANK, 0.03125f, nullptr, RS + N_ROIS);

    // ---- PV: F = (E Vt^T)/rsum   (1-term)
    gemm_f16<3,1,false><<<dim3(4, 32), blk, SM_T1>>>(E_h, nullptr, N_BANK,
        Vt_h, nullptr, N_BANK, N_BANK, F, nullptr, nullptr, LATENT, 0.f, nullptr, RS);
    gemm_f16<3,1,false><<<dim3(4, 32), blk, SM_T1>>>(E_h + SO, nullptr, N_BANK,
        Vt_h + VO, nullptr, N_BANK, N_BANK, F + QO, nullptr, nullptr, LATENT, 0.f, nullptr, RS + N_ROIS);

    // ---- gate + LN + PReLU -> X split
    gate_ln_kernel<<<N_ROIS, blk>>>(F, ln_w, ln_b, prelu_a, X_h, X_l);

    // ---- FFN (2-term)
    gemm_f16<4,2,false><<<dim3(8, 32), blk, SM_T2>>>(X_h, X_l, LATENT,
        W_h + 6 * WSZ, nullptr, LATENT, LATENT, out, nullptr, nullptr, DIM_IN, 0.f, bffn, nullptr);
}

// round 11
// speedup vs baseline: 1.6700x; 1.2187x over previous
#include <cuda_runtime.h>
#include <cuda_fp16.h>
#include <cstdint>
#include <math.h>

#define DIM_IN 2048
#define QDIM   2048
#define LATENT 1024
#define N_ROIS 4096
#define N_BANK 8192
#define LN_EPS 1e-5f

// ============================ static scratch ====================================
__device__ __half g_feat_h[(size_t)N_ROIS * QDIM];
__device__ __half g_kb_h[(size_t)N_BANK * DIM_IN];
#define WSZ ((size_t)LATENT * QDIM)
__device__ __half g_W_h[7 * WSZ];
__device__ __half g_Wf_l[WSZ];                 // lo plane only for FFN weight
__device__ __half g_Q_h[(size_t)2 * N_ROIS * LATENT];
__device__ __half g_K_h[(size_t)2 * N_BANK * LATENT];
__device__ __half g_Vt_h[(size_t)2 * LATENT * N_BANK];
__device__ __half g_E_h[(size_t)2 * N_ROIS * N_BANK];
__device__ float  g_F  [(size_t)2 * N_ROIS * LATENT];
__device__ __half g_X_h[(size_t)N_ROIS * LATENT];
__device__ __half g_X_l[(size_t)N_ROIS * LATENT];
__device__ float g_rsum[2 * N_ROIS];

// ============================ PTX helpers =======================================
__device__ __forceinline__ uint32_t smem_u32(const void* p) {
    uint32_t a;
    asm("{ .reg .u64 t; cvta.to.shared.u64 t, %1; cvt.u32.u64 %0, t; }" : "=r"(a) : "l"(p));
    return a;
}
__device__ __forceinline__ void cp_async16(uint32_t s, const void* g) {
    asm volatile("cp.async.cg.shared.global [%0], [%1], 16;\n" :: "r"(s), "l"(g));
}
#define CP_COMMIT() asm volatile("cp.async.commit_group;\n" ::: "memory")
#define CP_WAIT1()  asm volatile("cp.async.wait_group 1;\n" ::: "memory")

#define LDSM_X4(r, a)                                                               \
    asm volatile("ldmatrix.sync.aligned.m8n8.x4.shared.b16 {%0,%1,%2,%3}, [%4];"    \
        : "=r"((r)[0]), "=r"((r)[1]), "=r"((r)[2]), "=r"((r)[3]) : "r"(a))

#define MMA_F16(c, a, b0, b1)                                                       \
    asm volatile("mma.sync.aligned.m16n8k16.row.col.f32.f16.f16.f32 "               \
        "{%0,%1,%2,%3}, {%4,%5,%6,%7}, {%8,%9}, {%0,%1,%2,%3};"                     \
        : "+f"((c)[0]), "+f"((c)[1]), "+f"((c)[2]), "+f"((c)[3])                    \
        : "r"((a)[0]), "r"((a)[1]), "r"((a)[2]), "r"((a)[3]), "r"(b0), "r"(b1))

__device__ __forceinline__ void split16(float x, __half& h, __half& l) {
    h = __float2half_rn(x);
    l = __float2half_rn(x - __half2float(h));
}

// ============================ tiled split-fp16 MMA GEMM =========================
// C = A * B^T, fp32 accum.
// TERMS=1: hiA*hiB | TERMS=2: + loA*hiB | TERMS=3: + loA*hiB + hiA*loB
// MODE 0: fp16 out (+col-bias) | 1: fp16 out (+row-bias)
// MODE 3: f32 *1/rsum[row] | 4: f32 +col-bias
// MODE 5: e = exp(alpha*acc) -> fp16 out; atomicAdd row sums into rsum
// Block 128x256x32, 8 warps, warp 64x64, 3-stage cp.async.
#define A_TILE_B 10240
#define B_TILE_B 20480

template<int TERMS>
__device__ __forceinline__ void load_stage_g(uint32_t st,
    const __half* __restrict__ Ah, const __half* __restrict__ Al, int lda, int m0,
    const __half* __restrict__ Bh, const __half* __restrict__ Bl, int ldb, int n0,
    int k0, int tid)
{
    constexpr uint32_t B_OFF = (TERMS >= 2 ? 2u : 1u) * A_TILE_B;
#pragma unroll
    for (int it = 0; it < 2; ++it) {
        int id = tid + it * 256;
        int r  = id >> 2;
        int cw = id & 3;
        uint32_t soff = (uint32_t)(r * 80 + cw * 16);
        size_t ga = (size_t)(m0 + r) * lda + k0 + cw * 8;
        cp_async16(st + soff, Ah + ga);
        if (TERMS >= 2) cp_async16(st + A_TILE_B + soff, Al + ga);
    }
#pragma unroll
    for (int it = 0; it < 4; ++it) {
        int id = tid + it * 256;
        int r  = id >> 2;
        int cw = id & 3;
        uint32_t soff = (uint32_t)(r * 80 + cw * 16);
        size_t gb = (size_t)(n0 + r) * ldb + k0 + cw * 8;
        cp_async16(st + B_OFF + soff, Bh + gb);
        if (TERMS == 3) cp_async16(st + B_OFF + B_TILE_B + soff, Bl + gb);
    }
}

template<int MODE, int TERMS, bool SLO>
__global__ __launch_bounds__(256, 1)
void gemm_f16(const __half* __restrict__ Ah, const __half* __restrict__ Al, int lda,
              const __half* __restrict__ Bh, const __half* __restrict__ Bl, int ldb,
              int K,
              float* __restrict__ Cf,
              __half* __restrict__ Ch, __half* __restrict__ Cl, int ldc,
              float alpha, const float* __restrict__ bias, float* __restrict__ rsum)
{
    constexpr uint32_t B_OFF   = (TERMS >= 2 ? 2u : 1u) * A_TILE_B;
    constexpr uint32_t STAGE_B = B_OFF + (TERMS == 3 ? 2u : 1u) * B_TILE_B;
    extern __shared__ __align__(16) char smem[];
    const uint32_t sbase = smem_u32(smem);
    const int tid = threadIdx.x, wid = tid >> 5, lane = tid & 31;
    const int m0 = blockIdx.y * 128, n0 = blockIdx.x * 256;
    const int wm = wid & 1;
    const int wn = wid >> 1;

    const uint32_t aoff = (uint32_t)((wm * 64 + (lane & 15)) * 80 + (lane >> 4) * 16);
    const uint32_t boff = (uint32_t)((wn * 64 + ((lane >> 4) & 1) * 8 + (lane & 7)) * 80
                                     + ((lane >> 3) & 1) * 16);

    float acc[4][4][8];
#pragma unroll
    for (int i = 0; i < 4; i++)
#pragma unroll
        for (int j = 0; j < 4; j++)
#pragma unroll
            for (int q = 0; q < 8; q++) acc[i][j][q] = 0.f;

    const int nc = K >> 5;

    load_stage_g<TERMS>(sbase, Ah, Al, lda, m0, Bh, Bl, ldb, n0, 0, tid);
    CP_COMMIT();
    if (nc > 1) load_stage_g<TERMS>(sbase + STAGE_B, Ah, Al, lda, m0, Bh, Bl, ldb, n0, 32, tid);
    CP_COMMIT();

#pragma unroll 1
    for (int c = 0; c < nc; c++) {
        CP_WAIT1();
        __syncthreads();
        int cn = c + 2;
        if (cn < nc)
            load_stage_g<TERMS>(sbase + (uint32_t)(cn % 3) * STAGE_B, Ah, Al, lda, m0, Bh, Bl, ldb, n0, cn * 32, tid);
        CP_COMMIT();

        const uint32_t st  = sbase + (uint32_t)(c % 3) * STAGE_B;
        const uint32_t sAh = st, sAl = st + A_TILE_B;
        const uint32_t sBh = st + B_OFF;
        const uint32_t sBl = st + B_OFF + B_TILE_B;
#pragma unroll
        for (int ks = 0; ks < 2; ks++) {
            uint32_t ah[4][4], al[4][4];
#pragma unroll
            for (int mi = 0; mi < 4; mi++) {
                uint32_t off = aoff + (uint32_t)(mi * 1280 + ks * 32);
                LDSM_X4(ah[mi], sAh + off);
                if (TERMS >= 2) LDSM_X4(al[mi], sAl + off);
            }
#pragma unroll
            for (int p = 0; p < 4; p++) {
                uint32_t off = boff + (uint32_t)(p * 1280 + ks * 32);
                uint32_t bh[4];
                LDSM_X4(bh, sBh + off);
                if (TERMS == 3) {
                    uint32_t bl[4];
                    LDSM_X4(bl, sBl + off);
#pragma unroll
                    for (int mi = 0; mi < 4; mi++) {
                        MMA_F16((acc[mi][p] + 0), ah[mi], bh[0], bh[1]);
                        MMA_F16((acc[mi][p] + 4), ah[mi], bh[2], bh[3]);
                        MMA_F16((acc[mi][p] + 0), ah[mi], bl[0], bl[1]);
                        MMA_F16((acc[mi][p] + 4), ah[mi], bl[2], bl[3]);
                        MMA_F16((acc[mi][p] + 0), al[mi], bh[0], bh[1]);
                        MMA_F16((acc[mi][p] + 4), al[mi], bh[2], bh[3]);
                    }
                } else if (TERMS == 2) {
#pragma unroll
                    for (int mi = 0; mi < 4; mi++) {
                        MMA_F16((acc[mi][p] + 0), ah[mi], bh[0], bh[1]);
                        MMA_F16((acc[mi][p] + 4), ah[mi], bh[2], bh[3]);
                        MMA_F16((acc[mi][p] + 0), al[mi], bh[0], bh[1]);
                        MMA_F16((acc[mi][p] + 4), al[mi], bh[2], bh[3]);
                    }
                } else {
#pragma unroll
                    for (int mi = 0; mi < 4; mi++) {
                        MMA_F16((acc[mi][p] + 0), ah[mi], bh[0], bh[1]);
                        MMA_F16((acc[mi][p] + 4), ah[mi], bh[2], bh[3]);
                    }
                }
            }
        }
    }

    // ---- epilogue
#pragma unroll
    for (int mi = 0; mi < 4; mi++) {
        const int r0 = m0 + wm * 64 + mi * 16 + (lane >> 2);
        const int r1 = r0 + 8;
        float s0 = 1.f, s1 = 1.f, rb0 = 0.f, rb1 = 0.f;
        if (MODE == 3) { s0 = 1.f / rsum[r0]; s1 = 1.f / rsum[r1]; }
        if (MODE == 1) { rb0 = bias[r0]; rb1 = bias[r1]; }
        float rsum0 = 0.f, rsum1 = 0.f;
#pragma unroll
        for (int p = 0; p < 4; p++) {
#pragma unroll
            for (int n8 = 0; n8 < 2; n8++) {
                const int col = n0 + wn * 64 + p * 16 + n8 * 8 + 2 * (lane & 3);
                const float* a4 = acc[mi][p] + n8 * 4;
                float v0 = a4[0], v1 = a4[1], v2 = a4[2], v3 = a4[3];
                if (MODE == 5) {
                    v0 = __expf(v0 * alpha); v1 = __expf(v1 * alpha);
                    v2 = __expf(v2 * alpha); v3 = __expf(v3 * alpha);
                    rsum0 += v0 + v1; rsum1 += v2 + v3;
                    *reinterpret_cast<__half2*>(Ch + (size_t)r0 * ldc + col) =
                        __halves2half2(__float2half_rn(v0), __float2half_rn(v1));
                    *reinterpret_cast<__half2*>(Ch + (size_t)r1 * ldc + col) =
                        __halves2half2(__float2half_rn(v2), __float2half_rn(v3));
                    continue;
                }
                if (MODE == 3) { v0 *= s0; v1 *= s0; v2 *= s1; v3 *= s1; }
                if (MODE == 0 || MODE == 4) {
                    float b0 = bias[col], b1 = bias[col + 1];
                    v0 += b0; v1 += b1; v2 += b0; v3 += b1;
                }
                if (MODE == 1) { v0 += rb0; v1 += rb0; v2 += rb1; v3 += rb1; }

                if (MODE == 3 || MODE == 4) {
                    *reinterpret_cast<float2*>(Cf + (size_t)r0 * ldc + col) = make_float2(v0, v1);
                    *reinterpret_cast<float2*>(Cf + (size_t)r1 * ldc + col) = make_float2(v2, v3);
                } else {
                    __half h0, h1, h2, h3, l0, l1, l2, l3;
                    split16(v0, h0, l0); split16(v1, h1, l1);
                    split16(v2, h2, l2); split16(v3, h3, l3);
                    *reinterpret_cast<__half2*>(Ch + (size_t)r0 * ldc + col) = __halves2half2(h0, h1);
                    *reinterpret_cast<__half2*>(Ch + (size_t)r1 * ldc + col) = __halves2half2(h2, h3);
                    if (SLO) {
                        *reinterpret_cast<__half2*>(Cl + (size_t)r0 * ldc + col) = __halves2half2(l0, l1);
                        *reinterpret_cast<__half2*>(Cl + (size_t)r1 * ldc + col) = __halves2half2(l2, l3);
                    }
                }
            }
        }
        if (MODE == 5) {
            rsum0 += __shfl_xor_sync(0xffffffffu, rsum0, 1);
            rsum0 += __shfl_xor_sync(0xffffffffu, rsum0, 2);
            rsum1 += __shfl_xor_sync(0xffffffffu, rsum1, 1);
            rsum1 += __shfl_xor_sync(0xffffffffu, rsum1, 2);
            if ((lane & 3) == 0) {
                atomicAdd(rsum + r0, rsum0);
                atomicAdd(rsum + r1, rsum1);
            }
        }
    }
}

// ============================ aux kernels =======================================
// f32 -> fp16 hi only
__global__ __launch_bounds__(256)
void conv4_kernel(const float4* __restrict__ s, __half2* __restrict__ h, int n4)
{
    for (int i = blockIdx.x * blockDim.x + threadIdx.x; i < n4; i += gridDim.x * blockDim.x) {
        float4 v = s[i];
        h[2 * i + 0] = __halves2half2(__float2half_rn(v.x), __float2half_rn(v.y));
        h[2 * i + 1] = __halves2half2(__float2half_rn(v.z), __float2half_rn(v.w));
    }
}

// f32 -> fp16 hi + lo (FFN weight only)
__global__ __launch_bounds__(256)
void split4_kernel(const float4* __restrict__ s, __half2* __restrict__ h,
                   __half2* __restrict__ l, int n4)
{
    for (int i = blockIdx.x * blockDim.x + threadIdx.x; i < n4; i += gridDim.x * blockDim.x) {
        float4 v = s[i];
        __half hx, hy, hz, hw, lx, ly, lz, lw;
        split16(v.x, hx, lx); split16(v.y, hy, ly);
        split16(v.z, hz, lz); split16(v.w, hw, lw);
        h[2 * i + 0] = __halves2half2(hx, hy);
        h[2 * i + 1] = __halves2half2(hz, hw);
        l[2 * i + 0] = __halves2half2(lx, ly);
        l[2 * i + 1] = __halves2half2(lz, lw);
    }
}

__global__ __launch_bounds__(256)
void zero_kernel(float* __restrict__ p, int n)
{
    int i = blockIdx.x * blockDim.x + threadIdx.x;
    if (i < n) p[i] = 0.f;
}

__global__ __launch_bounds__(256)
void gate_ln_kernel(const float* __restrict__ F,
                    const float* __restrict__ ln_w, const float* __restrict__ ln_b,
                    const float* __restrict__ prelu_a,
                    __half* __restrict__ Xh, __half* __restrict__ Xl)
{
    const int row = blockIdx.x;
    const int t = threadIdx.x, lane = t & 31, w = t >> 5;
    const float4 f1 = reinterpret_cast<const float4*>(F + (size_t)row * LATENT)[t];
    const float4 f2 = reinterpret_cast<const float4*>(F + (size_t)(N_ROIS + row) * LATENT)[t];
    float4 c;
    c.x = f1.x * f2.x; c.y = f1.y * f2.y; c.z = f1.z * f2.z; c.w = f1.w * f2.w;

    __shared__ float red[8], mu_sh, var_sh;
    float s = c.x + c.y + c.z + c.w;
#pragma unroll
    for (int off = 16; off > 0; off >>= 1) s += __shfl_xor_sync(0xffffffffu, s, off);
    if (lane == 0) red[w] = s;
    __syncthreads();
    if (t == 0) {
        float ss = 0.f;
#pragma unroll
        for (int i = 0; i < 8; i++) ss += red[i];
        mu_sh = ss * (1.f / LATENT);
    }
    __syncthreads();
    const float mu = mu_sh;
    float dx = c.x - mu, dy = c.y - mu, dz = c.z - mu, dw = c.w - mu;
    float sq = dx * dx + dy * dy + dz * dz + dw * dw;
#pragma unroll
    for (int off = 16; off > 0; off >>= 1) sq += __shfl_xor_sync(0xffffffffu, sq, off);
    __syncthreads();
    if (lane == 0) red[w] = sq;
    __syncthreads();
    if (t == 0) {
        float ss = 0.f;
#pragma unroll
        for (int i = 0; i < 8; i++) ss += red[i];
        var_sh = ss * (1.f / LATENT);
    }
    __syncthreads();
    const float inv = rsqrtf(var_sh + LN_EPS);
    const float slope = prelu_a[0];
    const float4 wv = reinterpret_cast<const float4*>(ln_w)[t];
    const float4 bv = reinterpret_cast<const float4*>(ln_b)[t];
    float4 x;
    x.x = dx * inv * wv.x + bv.x;  x.y = dy * inv * wv.y + bv.y;
    x.z = dz * inv * wv.z + bv.z;  x.w = dw * inv * wv.w + bv.w;
    x.x = x.x >= 0.f ? x.x : slope * x.x;
    x.y = x.y >= 0.f ? x.y : slope * x.y;
    x.z = x.z >= 0.f ? x.z : slope * x.z;
    x.w = x.w >= 0.f ? x.w : slope * x.w;

    __half h0, h1, h2, h3, l0, l1, l2, l3;
    split16(x.x, h0, l0); split16(x.y, h1, l1);
    split16(x.z, h2, l2); split16(x.w, h3, l3);
    __half2* hp = reinterpret_cast<__half2*>(Xh + (size_t)row * LATENT);
    __half2* lp = reinterpret_cast<__half2*>(Xl + (size_t)row * LATENT);
    hp[2 * t + 0] = __halves2half2(h0, h1);
    hp[2 * t + 1] = __halves2half2(h2, h3);
    lp[2 * t + 0] = __halves2half2(l0, l1);
    lp[2 * t + 1] = __halves2half2(l2, l3);
}

// ============================ launch ============================================
static float* symf(const void* s) { void* p; cudaGetSymbolAddress(&p, s); return (float*)p; }
static __half* symh(const void* s) { void* p; cudaGetSymbolAddress(&p, s); return (__half*)p; }

extern "C" void kernel_launch(void* const* d_in, const int* in_sizes, int n_in,
                              void* d_out, int out_size)
{
    const float* feat     = (const float*)d_in[0];
    const float* key_bank = (const float*)d_in[1];
    const float* Wc1 = (const float*)d_in[2];  const float* bc1 = (const float*)d_in[3];
    const float* Wc2 = (const float*)d_in[4];  const float* bc2 = (const float*)d_in[5];
    const float* Wc3 = (const float*)d_in[6];  const float* bc3 = (const float*)d_in[7];
    const float* Wd1 = (const float*)d_in[8];  const float* bd1 = (const float*)d_in[9];
    const float* Wd2 = (const float*)d_in[10]; const float* bd2 = (const float*)d_in[11];
    const float* Wd3 = (const float*)d_in[12]; const float* bd3 = (const float*)d_in[13];
    const float* ln_w = (const float*)d_in[14];
    const float* ln_b = (const float*)d_in[15];
    const float* prelu_a = (const float*)d_in[16];
    const float* Wffn = (const float*)d_in[17];
    const float* bffn = (const float*)d_in[18];
    float* out = (float*)d_out;

    __half *feat_h = symh(&g_feat_h);
    __half *kb_h = symh(&g_kb_h);
    __half *W_h = symh(&g_W_h), *Wf_l = symh(&g_Wf_l);
    __half *Q_h = symh(&g_Q_h);
    __half *K_h = symh(&g_K_h);
    __half *Vt_h = symh(&g_Vt_h);
    __half *E_h = symh(&g_E_h);
    __half *X_h = symh(&g_X_h), *X_l = symh(&g_X_l);
    float *F = symf(&g_F), *RS = symf(&g_rsum);

    const int SM_T1 = 3 * (A_TILE_B + B_TILE_B);            // 92160
    const int SM_T2 = 3 * (2 * A_TILE_B + B_TILE_B);        // 122880
    cudaFuncSetAttribute(gemm_f16<0,1,false>, cudaFuncAttributeMaxDynamicSharedMemorySize, SM_T1);
    cudaFuncSetAttribute(gemm_f16<1,1,false>, cudaFuncAttributeMaxDynamicSharedMemorySize, SM_T1);
    cudaFuncSetAttribute(gemm_f16<5,1,false>, cudaFuncAttributeMaxDynamicSharedMemorySize, SM_T1);
    cudaFuncSetAttribute(gemm_f16<3,1,false>, cudaFuncAttributeMaxDynamicSharedMemorySize, SM_T1);
    cudaFuncSetAttribute(gemm_f16<4,2,false>, cudaFuncAttributeMaxDynamicSharedMemorySize, SM_T2);

    const dim3 blk(256);
    const int SG = 1184;

    // ---- convert inputs & weights to fp16 hi (FFN weight also lo)
    conv4_kernel<<<SG, blk>>>((const float4*)feat, (__half2*)feat_h, (int)((size_t)N_ROIS * QDIM / 4));
    conv4_kernel<<<SG, blk>>>((const float4*)key_bank, (__half2*)kb_h, (int)((size_t)N_BANK * DIM_IN / 4));
    const float* Ws[6] = { Wc1, Wd1, Wc2, Wd2, Wc3, Wd3 };
    for (int i = 0; i < 6; i++)
        conv4_kernel<<<SG, blk>>>((const float4*)Ws[i], (__half2*)(W_h + i * WSZ), (int)(WSZ / 4));
    split4_kernel<<<SG, blk>>>((const float4*)Wffn, (__half2*)(W_h + 6 * WSZ), (__half2*)Wf_l, (int)(WSZ / 4));
    zero_kernel<<<(2 * N_ROIS + 255) / 256, blk>>>(RS, 2 * N_ROIS);

    const size_t QO = (size_t)N_ROIS * LATENT;
    const size_t KO = (size_t)N_BANK * LATENT;
    const size_t VO = (size_t)LATENT * N_BANK;
    const size_t SO = (size_t)N_ROIS * N_BANK;

    // ---- Q projections (1-term)
    gemm_f16<0,1,false><<<dim3(4, 32), blk, SM_T1>>>(feat_h, nullptr, QDIM,
        W_h + 0 * WSZ, nullptr, QDIM, QDIM, nullptr, Q_h, nullptr, LATENT, 0.f, bc1, nullptr);
    gemm_f16<0,1,false><<<dim3(4, 32), blk, SM_T1>>>(feat_h, nullptr, QDIM,
        W_h + 1 * WSZ, nullptr, QDIM, QDIM, nullptr, Q_h + QO, nullptr, LATENT, 0.f, bd1, nullptr);
    // ---- K projections (1-term)
    gemm_f16<0,1,false><<<dim3(4, 64), blk, SM_T1>>>(kb_h, nullptr, DIM_IN,
        W_h + 2 * WSZ, nullptr, DIM_IN, DIM_IN, nullptr, K_h, nullptr, LATENT, 0.f, bc2, nullptr);
    gemm_f16<0,1,false><<<dim3(4, 64), blk, SM_T1>>>(kb_h, nullptr, DIM_IN,
        W_h + 3 * WSZ, nullptr, DIM_IN, DIM_IN, nullptr, K_h + KO, nullptr, LATENT, 0.f, bd2, nullptr);
    // ---- Vt projections (1-term, row bias)
    gemm_f16<1,1,false><<<dim3(32, 8), blk, SM_T1>>>(W_h + 4 * WSZ, nullptr, DIM_IN,
        kb_h, nullptr, DIM_IN, DIM_IN, nullptr, Vt_h, nullptr, N_BANK, 0.f, bc3, nullptr);
    gemm_f16<1,1,false><<<dim3(32, 8), blk, SM_T1>>>(W_h + 5 * WSZ, nullptr, DIM_IN,
        kb_h, nullptr, DIM_IN, DIM_IN, nullptr, Vt_h + VO, nullptr, N_BANK, 0.f, bd3, nullptr);

    // ---- scores + exp fused: E = exp((Q K^T)/32), rsum += row sums  (1-term)
    gemm_f16<5,1,false><<<dim3(32, 32), blk, SM_T1>>>(Q_h, nullptr, LATENT,
        K_h, nullptr, LATENT, LATENT, nullptr, E_h, nullptr, N_BANK, 0.03125f, nullptr, RS);
    gemm_f16<5,1,false><<<dim3(32, 32), blk, SM_T1>>>(Q_h + QO, nullptr, LATENT,
        K_h + KO, nullptr, LATENT, LATENT, nullptr, E_h + SO, nullptr, N_BANK, 0.03125f, nullptr, RS + N_ROIS);

    // ---- PV: F = (E Vt^T)/rsum   (1-term)
    gemm_f16<3,1,false><<<dim3(4, 32), blk, SM_T1>>>(E_h, nullptr, N_BANK,
        Vt_h, nullptr, N_BANK, N_BANK, F, nullptr, nullptr, LATENT, 0.f, nullptr, RS);
    gemm_f16<3,1,false><<<dim3(4, 32), blk, SM_T1>>>(E_h + SO, nullptr, N_BANK,
        Vt_h + VO, nullptr, N_BANK, N_BANK, F + QO, nullptr, nullptr, LATENT, 0.f, nullptr, RS + N_ROIS);

    // ---- gate + LN + PReLU -> X split
    gate_ln_kernel<<<N_ROIS, blk>>>(F, ln_w, ln_b, prelu_a, X_h, X_l);

    // ---- FFN (2-term: X hi+lo vs W hi)
    gemm_f16<4,2,false><<<dim3(8, 32), blk, SM_T2>>>(X_h, X_l, LATENT,
        W_h + 6 * WSZ, nullptr, LATENT, LATENT, out, nullptr, nullptr, DIM_IN, 0.f, bffn, nullptr);
}

// round 12
// speedup vs baseline: 1.7373x; 1.0403x over previous
#include <cuda_runtime.h>
#include <cuda_fp16.h>
#include <cstdint>
#include <math.h>

#define DIM_IN 2048
#define QDIM   2048
#define LATENT 1024
#define N_ROIS 4096
#define N_BANK 8192
#define LN_EPS 1e-5f

// ============================ static scratch ====================================
__device__ __half g_feat_h[(size_t)N_ROIS * QDIM];
__device__ __half g_kb_h[(size_t)N_BANK * DIM_IN];
#define WSZ ((size_t)LATENT * QDIM)
__device__ __half g_W_h[7 * WSZ];
__device__ __half g_Q_h[(size_t)2 * N_ROIS * LATENT];
__device__ __half g_K_h[(size_t)2 * N_BANK * LATENT];
__device__ __half g_Vt_h[(size_t)2 * LATENT * N_BANK];
__device__ __half g_E_h[(size_t)2 * N_ROIS * N_BANK];
__device__ float  g_F  [(size_t)2 * N_ROIS * LATENT];
__device__ __half g_X_h[(size_t)N_ROIS * LATENT];
__device__ float g_rsum[2 * N_ROIS];

// ============================ PTX helpers =======================================
__device__ __forceinline__ uint32_t smem_u32(const void* p) {
    uint32_t a;
    asm("{ .reg .u64 t; cvta.to.shared.u64 t, %1; cvt.u32.u64 %0, t; }" : "=r"(a) : "l"(p));
    return a;
}
__device__ __forceinline__ void cp_async16(uint32_t s, const void* g) {
    asm volatile("cp.async.cg.shared.global [%0], [%1], 16;\n" :: "r"(s), "l"(g));
}
#define CP_COMMIT() asm volatile("cp.async.commit_group;\n" ::: "memory")
#define CP_WAIT1()  asm volatile("cp.async.wait_group 1;\n" ::: "memory")

#define LDSM_X4(r, a)                                                               \
    asm volatile("ldmatrix.sync.aligned.m8n8.x4.shared.b16 {%0,%1,%2,%3}, [%4];"    \
        : "=r"((r)[0]), "=r"((r)[1]), "=r"((r)[2]), "=r"((r)[3]) : "r"(a))

#define MMA_F16(c, a, b0, b1)                                                       \
    asm volatile("mma.sync.aligned.m16n8k16.row.col.f32.f16.f16.f32 "               \
        "{%0,%1,%2,%3}, {%4,%5,%6,%7}, {%8,%9}, {%0,%1,%2,%3};"                     \
        : "+f"((c)[0]), "+f"((c)[1]), "+f"((c)[2]), "+f"((c)[3])                    \
        : "r"((a)[0]), "r"((a)[1]), "r"((a)[2]), "r"((a)[3]), "r"(b0), "r"(b1))

// ============================ tiled fp16 MMA GEMM ===============================
// C = A * B^T, fp32 accum, single-term (hiA*hiB).
// Batched over blockIdx.z via element strides zsA/zsB/zsC (+bias2 for z=1,
// rsum offset zrs).
// MODE 0: fp16 out (+col-bias) | 1: fp16 out (+row-bias)
// MODE 3: f32 *1/rsum[row] | 4: f32 +col-bias
// MODE 5: e = exp(alpha*acc) -> fp16 out; atomicAdd row sums into rsum
// Block 128x256x32, 8 warps, warp 64x64, 3-stage cp.async.
#define A_TILE_B 10240
#define B_TILE_B 20480
#define STAGE_B  30720
#define SMEM_G   (3 * STAGE_B)

__device__ __forceinline__ void load_stage_g(uint32_t st,
    const __half* __restrict__ Ah, int lda, int m0,
    const __half* __restrict__ Bh, int ldb, int n0, int k0, int tid)
{
#pragma unroll
    for (int it = 0; it < 2; ++it) {
        int id = tid + it * 256;
        int r  = id >> 2;
        int cw = id & 3;
        uint32_t soff = (uint32_t)(r * 80 + cw * 16);
        cp_async16(st + soff, Ah + (size_t)(m0 + r) * lda + k0 + cw * 8);
    }
#pragma unroll
    for (int it = 0; it < 4; ++it) {
        int id = tid + it * 256;
        int r  = id >> 2;
        int cw = id & 3;
        uint32_t soff = (uint32_t)(r * 80 + cw * 16);
        cp_async16(st + A_TILE_B + soff, Bh + (size_t)(n0 + r) * ldb + k0 + cw * 8);
    }
}

template<int MODE>
__global__ __launch_bounds__(256, 1)
void gemm_f16(const __half* __restrict__ Ah, int lda, size_t zsA,
              const __half* __restrict__ Bh, int ldb, size_t zsB,
              int K,
              float* __restrict__ Cf, __half* __restrict__ Ch, int ldc, size_t zsC,
              float alpha,
              const float* __restrict__ bias, const float* __restrict__ bias2,
              float* __restrict__ rsum, int zrs)
{
    extern __shared__ __align__(16) char smem[];
    const uint32_t sbase = smem_u32(smem);
    const int tid = threadIdx.x, wid = tid >> 5, lane = tid & 31;
    const int z = blockIdx.z;
    const int m0 = blockIdx.y * 128, n0 = blockIdx.x * 256;
    const int wm = wid & 1;
    const int wn = wid >> 1;

    Ah += (size_t)z * zsA;
    Bh += (size_t)z * zsB;
    if (Cf) Cf += (size_t)z * zsC;
    if (Ch) Ch += (size_t)z * zsC;
    const float* bptr = z ? bias2 : bias;
    if (rsum) rsum += (size_t)z * zrs;

    const uint32_t aoff = (uint32_t)((wm * 64 + (lane & 15)) * 80 + (lane >> 4) * 16);
    const uint32_t boff = (uint32_t)((wn * 64 + ((lane >> 4) & 1) * 8 + (lane & 7)) * 80
                                     + ((lane >> 3) & 1) * 16);

    float acc[4][4][8];
#pragma unroll
    for (int i = 0; i < 4; i++)
#pragma unroll
        for (int j = 0; j < 4; j++)
#pragma unroll
            for (int q = 0; q < 8; q++) acc[i][j][q] = 0.f;

    const int nc = K >> 5;

    load_stage_g(sbase, Ah, lda, m0, Bh, ldb, n0, 0, tid);
    CP_COMMIT();
    if (nc > 1) load_stage_g(sbase + STAGE_B, Ah, lda, m0, Bh, ldb, n0, 32, tid);
    CP_COMMIT();

#pragma unroll 1
    for (int c = 0; c < nc; c++) {
        CP_WAIT1();
        __syncthreads();
        int cn = c + 2;
        if (cn < nc)
            load_stage_g(sbase + (uint32_t)(cn % 3) * STAGE_B, Ah, lda, m0, Bh, ldb, n0, cn * 32, tid);
        CP_COMMIT();

        const uint32_t st  = sbase + (uint32_t)(c % 3) * STAGE_B;
        const uint32_t sAh = st, sBh = st + A_TILE_B;
#pragma unroll
        for (int ks = 0; ks < 2; ks++) {
            uint32_t ah[4][4];
#pragma unroll
            for (int mi = 0; mi < 4; mi++)
                LDSM_X4(ah[mi], sAh + aoff + (uint32_t)(mi * 1280 + ks * 32));
#pragma unroll
            for (int p = 0; p < 4; p++) {
                uint32_t bh[4];
                LDSM_X4(bh, sBh + boff + (uint32_t)(p * 1280 + ks * 32));
#pragma unroll
                for (int mi = 0; mi < 4; mi++) {
                    MMA_F16((acc[mi][p] + 0), ah[mi], bh[0], bh[1]);
                    MMA_F16((acc[mi][p] + 4), ah[mi], bh[2], bh[3]);
                }
            }
        }
    }

    // ---- epilogue
#pragma unroll
    for (int mi = 0; mi < 4; mi++) {
        const int r0 = m0 + wm * 64 + mi * 16 + (lane >> 2);
        const int r1 = r0 + 8;
        float s0 = 1.f, s1 = 1.f, rb0 = 0.f, rb1 = 0.f;
        if (MODE == 3) { s0 = 1.f / rsum[r0]; s1 = 1.f / rsum[r1]; }
        if (MODE == 1) { rb0 = bptr[r0]; rb1 = bptr[r1]; }
        float rsum0 = 0.f, rsum1 = 0.f;
#pragma unroll
        for (int p = 0; p < 4; p++) {
#pragma unroll
            for (int n8 = 0; n8 < 2; n8++) {
                const int col = n0 + wn * 64 + p * 16 + n8 * 8 + 2 * (lane & 3);
                const float* a4 = acc[mi][p] + n8 * 4;
                float v0 = a4[0], v1 = a4[1], v2 = a4[2], v3 = a4[3];
                if (MODE == 5) {
                    v0 = __expf(v0 * alpha); v1 = __expf(v1 * alpha);
                    v2 = __expf(v2 * alpha); v3 = __expf(v3 * alpha);
                    rsum0 += v0 + v1; rsum1 += v2 + v3;
                    *reinterpret_cast<__half2*>(Ch + (size_t)r0 * ldc + col) =
                        __halves2half2(__float2half_rn(v0), __float2half_rn(v1));
                    *reinterpret_cast<__half2*>(Ch + (size_t)r1 * ldc + col) =
                        __halves2half2(__float2half_rn(v2), __float2half_rn(v3));
                    continue;
                }
                if (MODE == 3) { v0 *= s0; v1 *= s0; v2 *= s1; v3 *= s1; }
                if (MODE == 0 || MODE == 4) {
                    float b0 = bptr[col], b1 = bptr[col + 1];
                    v0 += b0; v1 += b1; v2 += b0; v3 += b1;
                }
                if (MODE == 1) { v0 += rb0; v1 += rb0; v2 += rb1; v3 += rb1; }

                if (MODE == 3 || MODE == 4) {
                    *reinterpret_cast<float2*>(Cf + (size_t)r0 * ldc + col) = make_float2(v0, v1);
                    *reinterpret_cast<float2*>(Cf + (size_t)r1 * ldc + col) = make_float2(v2, v3);
                } else {
                    *reinterpret_cast<__half2*>(Ch + (size_t)r0 * ldc + col) =
                        __halves2half2(__float2half_rn(v0), __float2half_rn(v1));
                    *reinterpret_cast<__half2*>(Ch + (size_t)r1 * ldc + col) =
                        __halves2half2(__float2half_rn(v2), __float2half_rn(v3));
                }
            }
        }
        if (MODE == 5) {
            rsum0 += __shfl_xor_sync(0xffffffffu, rsum0, 1);
            rsum0 += __shfl_xor_sync(0xffffffffu, rsum0, 2);
            rsum1 += __shfl_xor_sync(0xffffffffu, rsum1, 1);
            rsum1 += __shfl_xor_sync(0xffffffffu, rsum1, 2);
            if ((lane & 3) == 0) {
                atomicAdd(rsum + r0, rsum0);
                atomicAdd(rsum + r1, rsum1);
            }
        }
    }
}

// ============================ aux kernels =======================================
__global__ __launch_bounds__(256)
void conv4_kernel(const float4* __restrict__ s, __half2* __restrict__ h, int n4)
{
    for (int i = blockIdx.x * blockDim.x + threadIdx.x; i < n4; i += gridDim.x * blockDim.x) {
        float4 v = s[i];
        h[2 * i + 0] = __halves2half2(__float2half_rn(v.x), __float2half_rn(v.y));
        h[2 * i + 1] = __halves2half2(__float2half_rn(v.z), __float2half_rn(v.w));
    }
}

// convert 7 weight matrices (each WSZ elements) in one launch
struct W7 { const float4* p[7]; };
#define W_N4 ((int)(WSZ / 4))   // 524288 = 2^19
__global__ __launch_bounds__(256)
void conv7_kernel(W7 ws, __half2* __restrict__ h)
{
    const int total = 7 * W_N4;
    for (int i = blockIdx.x * blockDim.x + threadIdx.x; i < total; i += gridDim.x * blockDim.x) {
        int seg = i >> 19;
        int j   = i & (W_N4 - 1);
        float4 v = ws.p[seg][j];
        h[2 * (size_t)i + 0] = __halves2half2(__float2half_rn(v.x), __float2half_rn(v.y));
        h[2 * (size_t)i + 1] = __halves2half2(__float2half_rn(v.z), __float2half_rn(v.w));
    }
}

__global__ __launch_bounds__(256)
void zero_kernel(float* __restrict__ p, int n)
{
    int i = blockIdx.x * blockDim.x + threadIdx.x;
    if (i < n) p[i] = 0.f;
}

__global__ __launch_bounds__(256)
void gate_ln_kernel(const float* __restrict__ F,
                    const float* __restrict__ ln_w, const float* __restrict__ ln_b,
                    const float* __restrict__ prelu_a,
                    __half* __restrict__ Xh)
{
    const int row = blockIdx.x;
    const int t = threadIdx.x, lane = t & 31, w = t >> 5;
    const float4 f1 = reinterpret_cast<const float4*>(F + (size_t)row * LATENT)[t];
    const float4 f2 = reinterpret_cast<const float4*>(F + (size_t)(N_ROIS + row) * LATENT)[t];
    float4 c;
    c.x = f1.x * f2.x; c.y = f1.y * f2.y; c.z = f1.z * f2.z; c.w = f1.w * f2.w;

    __shared__ float red[8], mu_sh, var_sh;
    float s = c.x + c.y + c.z + c.w;
#pragma unroll
    for (int off = 16; off > 0; off >>= 1) s += __shfl_xor_sync(0xffffffffu, s, off);
    if (lane == 0) red[w] = s;
    __syncthreads();
    if (t == 0) {
        float ss = 0.f;
#pragma unroll
        for (int i = 0; i < 8; i++) ss += red[i];
        mu_sh = ss * (1.f / LATENT);
    }
    __syncthreads();
    const float mu = mu_sh;
    float dx = c.x - mu, dy = c.y - mu, dz = c.z - mu, dw = c.w - mu;
    float sq = dx * dx + dy * dy + dz * dz + dw * dw;
#pragma unroll
    for (int off = 16; off > 0; off >>= 1) sq += __shfl_xor_sync(0xffffffffu, sq, off);
    __syncthreads();
    if (lane == 0) red[w] = sq;
    __syncthreads();
    if (t == 0) {
        float ss = 0.f;
#pragma unroll
        for (int i = 0; i < 8; i++) ss += red[i];
        var_sh = ss * (1.f / LATENT);
    }
    __syncthreads();
    const float inv = rsqrtf(var_sh + LN_EPS);
    const float slope = prelu_a[0];
    const float4 wv = reinterpret_cast<const float4*>(ln_w)[t];
    const float4 bv = reinterpret_cast<const float4*>(ln_b)[t];
    float4 x;
    x.x = dx * inv * wv.x + bv.x;  x.y = dy * inv * wv.y + bv.y;
    x.z = dz * inv * wv.z + bv.z;  x.w = dw * inv * wv.w + bv.w;
    x.x = x.x >= 0.f ? x.x : slope * x.x;
    x.y = x.y >= 0.f ? x.y : slope * x.y;
    x.z = x.z >= 0.f ? x.z : slope * x.z;
    x.w = x.w >= 0.f ? x.w : slope * x.w;

    __half2* hp = reinterpret_cast<__half2*>(Xh + (size_t)row * LATENT);
    hp[2 * t + 0] = __halves2half2(__float2half_rn(x.x), __float2half_rn(x.y));
    hp[2 * t + 1] = __halves2half2(__float2half_rn(x.z), __float2half_rn(x.w));
}

// ============================ launch ============================================
static float* symf(const void* s) { void* p; cudaGetSymbolAddress(&p, s); return (float*)p; }
static __half* symh(const void* s) { void* p; cudaGetSymbolAddress(&p, s); return (__half*)p; }

extern "C" void kernel_launch(void* const* d_in, const int* in_sizes, int n_in,
                              void* d_out, int out_size)
{
    const float* feat     = (const float*)d_in[0];
    const float* key_bank = (const float*)d_in[1];
    const float* Wc1 = (const float*)d_in[2];  const float* bc1 = (const float*)d_in[3];
    const float* Wc2 = (const float*)d_in[4];  const float* bc2 = (const float*)d_in[5];
    const float* Wc3 = (const float*)d_in[6];  const float* bc3 = (const float*)d_in[7];
    const float* Wd1 = (const float*)d_in[8];  const float* bd1 = (const float*)d_in[9];
    const float* Wd2 = (const float*)d_in[10]; const float* bd2 = (const float*)d_in[11];
    const float* Wd3 = (const float*)d_in[12]; const float* bd3 = (const float*)d_in[13];
    const float* ln_w = (const float*)d_in[14];
    const float* ln_b = (const float*)d_in[15];
    const float* prelu_a = (const float*)d_in[16];
    const float* Wffn = (const float*)d_in[17];
    const float* bffn = (const float*)d_in[18];
    float* out = (float*)d_out;

    __half *feat_h = symh(&g_feat_h);
    __half *kb_h = symh(&g_kb_h);
    __half *W_h = symh(&g_W_h);
    __half *Q_h = symh(&g_Q_h);
    __half *K_h = symh(&g_K_h);
    __half *Vt_h = symh(&g_Vt_h);
    __half *E_h = symh(&g_E_h);
    __half *X_h = symh(&g_X_h);
    float *F = symf(&g_F), *RS = symf(&g_rsum);

    cudaFuncSetAttribute(gemm_f16<0>, cudaFuncAttributeMaxDynamicSharedMemorySize, SMEM_G);
    cudaFuncSetAttribute(gemm_f16<1>, cudaFuncAttributeMaxDynamicSharedMemorySize, SMEM_G);
    cudaFuncSetAttribute(gemm_f16<3>, cudaFuncAttributeMaxDynamicSharedMemorySize, SMEM_G);
    cudaFuncSetAttribute(gemm_f16<4>, cudaFuncAttributeMaxDynamicSharedMemorySize, SMEM_G);
    cudaFuncSetAttribute(gemm_f16<5>, cudaFuncAttributeMaxDynamicSharedMemorySize, SMEM_G);

    const dim3 blk(256);
    const int SG = 1184;

    // ---- convert inputs + all 7 weights to fp16
    conv4_kernel<<<SG, blk>>>((const float4*)feat, (__half2*)feat_h, (int)((size_t)N_ROIS * QDIM / 4));
    conv4_kernel<<<SG, blk>>>((const float4*)key_bank, (__half2*)kb_h, (int)((size_t)N_BANK * DIM_IN / 4));
    W7 ws;
    ws.p[0] = (const float4*)Wc1; ws.p[1] = (const float4*)Wd1;
    ws.p[2] = (const float4*)Wc2; ws.p[3] = (const float4*)Wd2;
    ws.p[4] = (const float4*)Wc3; ws.p[5] = (const float4*)Wd3;
    ws.p[6] = (const float4*)Wffn;
    conv7_kernel<<<SG, blk>>>(ws, (__half2*)W_h);
    zero_kernel<<<(2 * N_ROIS + 255) / 256, blk>>>(RS, 2 * N_ROIS);

    const size_t QO = (size_t)N_ROIS * LATENT;
    const size_t KO = (size_t)N_BANK * LATENT;
    const size_t VO = (size_t)LATENT * N_BANK;
    const size_t SO = (size_t)N_ROIS * N_BANK;

    // ---- Q projections, both branches (z)
    gemm_f16<0><<<dim3(4, 32, 2), blk, SMEM_G>>>(feat_h, QDIM, 0,
        W_h, QDIM, WSZ, QDIM, nullptr, Q_h, LATENT, QO, 0.f, bc1, bd1, nullptr, 0);
    // ---- K projections, both branches
    gemm_f16<0><<<dim3(4, 64, 2), blk, SMEM_G>>>(kb_h, DIM_IN, 0,
        W_h + 2 * WSZ, DIM_IN, WSZ, DIM_IN, nullptr, K_h, LATENT, KO, 0.f, bc2, bd2, nullptr, 0);
    // ---- Vt projections, both branches (row bias)
    gemm_f16<1><<<dim3(32, 8, 2), blk, SMEM_G>>>(W_h + 4 * WSZ, DIM_IN, WSZ,
        kb_h, DIM_IN, 0, DIM_IN, nullptr, Vt_h, N_BANK, VO, 0.f, bc3, bd3, nullptr, 0);

    // ---- scores + exp fused, both branches
    gemm_f16<5><<<dim3(32, 32, 2), blk, SMEM_G>>>(Q_h, LATENT, QO,
        K_h, LATENT, KO, LATENT, nullptr, E_h, N_BANK, SO, 0.03125f, nullptr, nullptr, RS, N_ROIS);

    // ---- PV, both branches
    gemm_f16<3><<<dim3(4, 32, 2), blk, SMEM_G>>>(E_h, N_BANK, SO,
        Vt_h, N_BANK, VO, N_BANK, F, nullptr, LATENT, QO, 0.f, nullptr, nullptr, RS, N_ROIS);

    // ---- gate + LN + PReLU -> X (fp16 hi only)
    gate_ln_kernel<<<N_ROIS, blk>>>(F, ln_w, ln_b, prelu_a, X_h);

    // ---- FFN (1-term)
    gemm_f16<4><<<dim3(8, 32, 1), blk, SMEM_G>>>(X_h, LATENT, 0,
        W_h + 6 * WSZ, LATENT, 0, LATENT, out, nullptr, DIM_IN, 0, 0.f, bffn, nullptr, nullptr, 0);
}

// round 13
// speedup vs baseline: 1.7723x; 1.0201x over previous
#include <cuda_runtime.h>
#include <cuda_fp16.h>
#include <cstdint>
#include <math.h>

#define DIM_IN 2048
#define QDIM   2048
#define LATENT 1024
#define N_ROIS 4096
#define N_BANK 8192
#define LN_EPS 1e-5f

// ============================ static scratch ====================================
__device__ __half g_feat_h[(size_t)N_ROIS * QDIM];
__device__ __half g_kb_h[(size_t)N_BANK * DIM_IN];
#define WSZ ((size_t)LATENT * QDIM)
__device__ __half g_W_h[7 * WSZ];
__device__ __half g_Q_h[(size_t)2 * N_ROIS * LATENT];
__device__ __half g_K_h[(size_t)2 * N_BANK * LATENT];
__device__ __half g_Vt_h[(size_t)2 * LATENT * N_BANK];
__device__ __half g_E_h[(size_t)2 * N_ROIS * N_BANK];
__device__ float  g_F  [(size_t)2 * N_ROIS * LATENT];
__device__ __half g_X_h[(size_t)N_ROIS * LATENT];
__device__ float g_rsum[2 * N_ROIS];

// ============================ PTX helpers =======================================
__device__ __forceinline__ uint32_t smem_u32(const void* p) {
    uint32_t a;
    asm("{ .reg .u64 t; cvta.to.shared.u64 t, %1; cvt.u32.u64 %0, t; }" : "=r"(a) : "l"(p));
    return a;
}
__device__ __forceinline__ void cp_async16(uint32_t s, const void* g) {
    asm volatile("cp.async.cg.shared.global [%0], [%1], 16;\n" :: "r"(s), "l"(g));
}
#define CP_COMMIT() asm volatile("cp.async.commit_group;\n" ::: "memory")
#define CP_WAIT1()  asm volatile("cp.async.wait_group 1;\n" ::: "memory")

#define LDSM_X4(r, a)                                                               \
    asm volatile("ldmatrix.sync.aligned.m8n8.x4.shared.b16 {%0,%1,%2,%3}, [%4];"    \
        : "=r"((r)[0]), "=r"((r)[1]), "=r"((r)[2]), "=r"((r)[3]) : "r"(a))

#define MMA_F16(c, a, b0, b1)                                                       \
    asm volatile("mma.sync.aligned.m16n8k16.row.col.f32.f16.f16.f32 "               \
        "{%0,%1,%2,%3}, {%4,%5,%6,%7}, {%8,%9}, {%0,%1,%2,%3};"                     \
        : "+f"((c)[0]), "+f"((c)[1]), "+f"((c)[2]), "+f"((c)[3])                    \
        : "r"((a)[0]), "r"((a)[1]), "r"((a)[2]), "r"((a)[3]), "r"(b0), "r"(b1))

// ============================ common GEMM pieces ================================
// Block 128x256x32, 8 warps, warp 64x64, 3-stage cp.async, single-term fp16.
#define A_TILE_B 10240
#define B_TILE_B 20480
#define STAGE_B  30720
#define SMEM_G   (3 * STAGE_B)

__device__ __forceinline__ void load_stage_g(uint32_t st,
    const __half* __restrict__ Ah, int lda, int m0,
    const __half* __restrict__ Bh, int ldb, int n0, int k0, int tid)
{
#pragma unroll
    for (int it = 0; it < 2; ++it) {
        int id = tid + it * 256;
        int r  = id >> 2;
        int cw = id & 3;
        uint32_t soff = (uint32_t)(r * 80 + cw * 16);
        cp_async16(st + soff, Ah + (size_t)(m0 + r) * lda + k0 + cw * 8);
    }
#pragma unroll
    for (int it = 0; it < 4; ++it) {
        int id = tid + it * 256;
        int r  = id >> 2;
        int cw = id & 3;
        uint32_t soff = (uint32_t)(r * 80 + cw * 16);
        cp_async16(st + A_TILE_B + soff, Bh + (size_t)(n0 + r) * ldb + k0 + cw * 8);
    }
}

// mainloop (shared by both kernels); accumulates into acc
__device__ __forceinline__ void gemm_mainloop(uint32_t sbase,
    const __half* __restrict__ Ah, int lda, int m0,
    const __half* __restrict__ Bh, int ldb, int n0, int K, int tid,
    uint32_t aoff, uint32_t boff, float acc[4][4][8])
{
    const int nc = K >> 5;
    load_stage_g(sbase, Ah, lda, m0, Bh, ldb, n0, 0, tid);
    CP_COMMIT();
    if (nc > 1) load_stage_g(sbase + STAGE_B, Ah, lda, m0, Bh, ldb, n0, 32, tid);
    CP_COMMIT();

#pragma unroll 1
    for (int c = 0; c < nc; c++) {
        CP_WAIT1();
        __syncthreads();
        int cn = c + 2;
        if (cn < nc)
            load_stage_g(sbase + (uint32_t)(cn % 3) * STAGE_B, Ah, lda, m0, Bh, ldb, n0, cn * 32, tid);
        CP_COMMIT();

        const uint32_t st  = sbase + (uint32_t)(c % 3) * STAGE_B;
        const uint32_t sAh = st, sBh = st + A_TILE_B;
#pragma unroll
        for (int ks = 0; ks < 2; ks++) {
            uint32_t ah[4][4];
#pragma unroll
            for (int mi = 0; mi < 4; mi++)
                LDSM_X4(ah[mi], sAh + aoff + (uint32_t)(mi * 1280 + ks * 32));
#pragma unroll
            for (int p = 0; p < 4; p++) {
                uint32_t bh[4];
                LDSM_X4(bh, sBh + boff + (uint32_t)(p * 1280 + ks * 32));
#pragma unroll
                for (int mi = 0; mi < 4; mi++) {
                    MMA_F16((acc[mi][p] + 0), ah[mi], bh[0], bh[1]);
                    MMA_F16((acc[mi][p] + 4), ah[mi], bh[2], bh[3]);
                }
            }
        }
    }
}

// ============================ fat projection GEMM ===============================
// 6 segments (Q b0/b1, K b0/b1, Vt b0/b1); all K=2048, fp16 out + bias.
struct GSeg {
    const __half* A; const __half* B; __half* C;
    int lda, ldb, ldc, nx, base, rowbias;
    const float* bias;
};
struct GSegs { GSeg s[6]; };

__global__ __launch_bounds__(256, 1)
void gemm_proj(GSegs segs)
{
    extern __shared__ __align__(16) char smem[];
    const uint32_t sbase = smem_u32(smem);
    const int tid = threadIdx.x, wid = tid >> 5, lane = tid & 31;
    const int bid = blockIdx.x;

    int si = 0;
#pragma unroll
    for (int i = 1; i < 6; i++) if (bid >= segs.s[i].base) si = i;
    const GSeg sg = segs.s[si];
    const int lid = bid - sg.base;
    const int m0 = (lid / sg.nx) * 128;
    const int n0 = (lid % sg.nx) * 256;
    const int wm = wid & 1, wn = wid >> 1;

    const uint32_t aoff = (uint32_t)((wm * 64 + (lane & 15)) * 80 + (lane >> 4) * 16);
    const uint32_t boff = (uint32_t)((wn * 64 + ((lane >> 4) & 1) * 8 + (lane & 7)) * 80
                                     + ((lane >> 3) & 1) * 16);

    float acc[4][4][8];
#pragma unroll
    for (int i = 0; i < 4; i++)
#pragma unroll
        for (int j = 0; j < 4; j++)
#pragma unroll
            for (int q = 0; q < 8; q++) acc[i][j][q] = 0.f;

    gemm_mainloop(sbase, sg.A, sg.lda, m0, sg.B, sg.ldb, n0, QDIM, tid, aoff, boff, acc);

    // ---- epilogue: fp16 out, col-bias or row-bias
#pragma unroll
    for (int mi = 0; mi < 4; mi++) {
        const int r0 = m0 + wm * 64 + mi * 16 + (lane >> 2);
        const int r1 = r0 + 8;
        float rb0 = 0.f, rb1 = 0.f;
        if (sg.rowbias) { rb0 = sg.bias[r0]; rb1 = sg.bias[r1]; }
#pragma unroll
        for (int p = 0; p < 4; p++) {
#pragma unroll
            for (int n8 = 0; n8 < 2; n8++) {
                const int col = n0 + wn * 64 + p * 16 + n8 * 8 + 2 * (lane & 3);
                const float* a4 = acc[mi][p] + n8 * 4;
                float v0 = a4[0], v1 = a4[1], v2 = a4[2], v3 = a4[3];
                if (sg.rowbias) {
                    v0 += rb0; v1 += rb0; v2 += rb1; v3 += rb1;
                } else {
                    float b0 = sg.bias[col], b1 = sg.bias[col + 1];
                    v0 += b0; v1 += b1; v2 += b0; v3 += b1;
                }
                *reinterpret_cast<__half2*>(sg.C + (size_t)r0 * sg.ldc + col) =
                    __halves2half2(__float2half_rn(v0), __float2half_rn(v1));
                *reinterpret_cast<__half2*>(sg.C + (size_t)r1 * sg.ldc + col) =
                    __halves2half2(__float2half_rn(v2), __float2half_rn(v3));
            }
        }
    }
}

// ============================ templated GEMM (scores/PV/FFN) ====================
// MODE 3: f32 *1/rsum[row] | 4: f32 +col-bias
// MODE 5: e = exp(alpha*acc) -> fp16 out; atomicAdd row sums into rsum
template<int MODE>
__global__ __launch_bounds__(256, 1)
void gemm_f16(const __half* __restrict__ Ah, int lda, size_t zsA,
              const __half* __restrict__ Bh, int ldb, size_t zsB,
              int K,
              float* __restrict__ Cf, __half* __restrict__ Ch, int ldc, size_t zsC,
              float alpha, const float* __restrict__ bias,
              float* __restrict__ rsum, int zrs)
{
    extern __shared__ __align__(16) char smem[];
    const uint32_t sbase = smem_u32(smem);
    const int tid = threadIdx.x, wid = tid >> 5, lane = tid & 31;
    const int z = blockIdx.z;
    const int m0 = blockIdx.y * 128, n0 = blockIdx.x * 256;
    const int wm = wid & 1, wn = wid >> 1;

    Ah += (size_t)z * zsA;
    Bh += (size_t)z * zsB;
    if (Cf) Cf += (size_t)z * zsC;
    if (Ch) Ch += (size_t)z * zsC;
    if (rsum) rsum += (size_t)z * zrs;

    const uint32_t aoff = (uint32_t)((wm * 64 + (lane & 15)) * 80 + (lane >> 4) * 16);
    const uint32_t boff = (uint32_t)((wn * 64 + ((lane >> 4) & 1) * 8 + (lane & 7)) * 80
                                     + ((lane >> 3) & 1) * 16);

    float acc[4][4][8];
#pragma unroll
    for (int i = 0; i < 4; i++)
#pragma unroll
        for (int j = 0; j < 4; j++)
#pragma unroll
            for (int q = 0; q < 8; q++) acc[i][j][q] = 0.f;

    gemm_mainloop(sbase, Ah, lda, m0, Bh, ldb, n0, K, tid, aoff, boff, acc);

    // ---- epilogue
#pragma unroll
    for (int mi = 0; mi < 4; mi++) {
        const int r0 = m0 + wm * 64 + mi * 16 + (lane >> 2);
        const int r1 = r0 + 8;
        float s0 = 1.f, s1 = 1.f;
        if (MODE == 3) { s0 = 1.f / rsum[r0]; s1 = 1.f / rsum[r1]; }
        float rsum0 = 0.f, rsum1 = 0.f;
#pragma unroll
        for (int p = 0; p < 4; p++) {
#pragma unroll
            for (int n8 = 0; n8 < 2; n8++) {
                const int col = n0 + wn * 64 + p * 16 + n8 * 8 + 2 * (lane & 3);
                const float* a4 = acc[mi][p] + n8 * 4;
                float v0 = a4[0], v1 = a4[1], v2 = a4[2], v3 = a4[3];
                if (MODE == 5) {
                    v0 = __expf(v0 * alpha); v1 = __expf(v1 * alpha);
                    v2 = __expf(v2 * alpha); v3 = __expf(v3 * alpha);
                    rsum0 += v0 + v1; rsum1 += v2 + v3;
                    *reinterpret_cast<__half2*>(Ch + (size_t)r0 * ldc + col) =
                        __halves2half2(__float2half_rn(v0), __float2half_rn(v1));
                    *reinterpret_cast<__half2*>(Ch + (size_t)r1 * ldc + col) =
                        __halves2half2(__float2half_rn(v2), __float2half_rn(v3));
                    continue;
                }
                if (MODE == 3) { v0 *= s0; v1 *= s0; v2 *= s1; v3 *= s1; }
                if (MODE == 4) {
                    float b0 = bias[col], b1 = bias[col + 1];
                    v0 += b0; v1 += b1; v2 += b0; v3 += b1;
                }
                *reinterpret_cast<float2*>(Cf + (size_t)r0 * ldc + col) = make_float2(v0, v1);
                *reinterpret_cast<float2*>(Cf + (size_t)r1 * ldc + col) = make_float2(v2, v3);
            }
        }
        if (MODE == 5) {
            rsum0 += __shfl_xor_sync(0xffffffffu, rsum0, 1);
            rsum0 += __shfl_xor_sync(0xffffffffu, rsum0, 2);
            rsum1 += __shfl_xor_sync(0xffffffffu, rsum1, 1);
            rsum1 += __shfl_xor_sync(0xffffffffu, rsum1, 2);
            if ((lane & 3) == 0) {
                atomicAdd(rsum + r0, rsum0);
                atomicAdd(rsum + r1, rsum1);
            }
        }
    }
}

// ============================ aux kernels =======================================
// convert 9 f32 segments to fp16 in one launch
struct C9 { const float4* src[9]; __half2* dst[9]; int n4[9]; };
__global__ __launch_bounds__(256)
void conv9_kernel(C9 c)
{
#pragma unroll 1
    for (int s = 0; s < 9; s++) {
        const float4* sp = c.src[s];
        __half2* dp = c.dst[s];
        const int n = c.n4[s];
        for (int i = blockIdx.x * blockDim.x + threadIdx.x; i < n; i += gridDim.x * blockDim.x) {
            float4 v = sp[i];
            dp[2 * i + 0] = __halves2half2(__float2half_rn(v.x), __float2half_rn(v.y));
            dp[2 * i + 1] = __halves2half2(__float2half_rn(v.z), __float2half_rn(v.w));
        }
    }
}

__global__ __launch_bounds__(256)
void zero_kernel(float* __restrict__ p, int n)
{
    int i = blockIdx.x * blockDim.x + threadIdx.x;
    if (i < n) p[i] = 0.f;
}

__global__ __launch_bounds__(256)
void gate_ln_kernel(const float* __restrict__ F,
                    const float* __restrict__ ln_w, const float* __restrict__ ln_b,
                    const float* __restrict__ prelu_a,
                    __half* __restrict__ Xh)
{
    const int row = blockIdx.x;
    const int t = threadIdx.x, lane = t & 31, w = t >> 5;
    const float4 f1 = reinterpret_cast<const float4*>(F + (size_t)row * LATENT)[t];
    const float4 f2 = reinterpret_cast<const float4*>(F + (size_t)(N_ROIS + row) * LATENT)[t];
    float4 c;
    c.x = f1.x * f2.x; c.y = f1.y * f2.y; c.z = f1.z * f2.z; c.w = f1.w * f2.w;

    __shared__ float red[8], mu_sh, var_sh;
    float s = c.x + c.y + c.z + c.w;
#pragma unroll
    for (int off = 16; off > 0; off >>= 1) s += __shfl_xor_sync(0xffffffffu, s, off);
    if (lane == 0) red[w] = s;
    __syncthreads();
    if (t == 0) {
        float ss = 0.f;
#pragma unroll
        for (int i = 0; i < 8; i++) ss += red[i];
        mu_sh = ss * (1.f / LATENT);
    }
    __syncthreads();
    const float mu = mu_sh;
    float dx = c.x - mu, dy = c.y - mu, dz = c.z - mu, dw = c.w - mu;
    float sq = dx * dx + dy * dy + dz * dz + dw * dw;
#pragma unroll
    for (int off = 16; off > 0; off >>= 1) sq += __shfl_xor_sync(0xffffffffu, sq, off);
    __syncthreads();
    if (lane == 0) red[w] = sq;
    __syncthreads();
    if (t == 0) {
        float ss = 0.f;
#pragma unroll
        for (int i = 0; i < 8; i++) ss += red[i];
        var_sh = ss * (1.f / LATENT);
    }
    __syncthreads();
    const float inv = rsqrtf(var_sh + LN_EPS);
    const float slope = prelu_a[0];
    const float4 wv = reinterpret_cast<const float4*>(ln_w)[t];
    const float4 bv = reinterpret_cast<const float4*>(ln_b)[t];
    float4 x;
    x.x = dx * inv * wv.x + bv.x;  x.y = dy * inv * wv.y + bv.y;
    x.z = dz * inv * wv.z + bv.z;  x.w = dw * inv * wv.w + bv.w;
    x.x = x.x >= 0.f ? x.x : slope * x.x;
    x.y = x.y >= 0.f ? x.y : slope * x.y;
    x.z = x.z >= 0.f ? x.z : slope * x.z;
    x.w = x.w >= 0.f ? x.w : slope * x.w;

    __half2* hp = reinterpret_cast<__half2*>(Xh + (size_t)row * LATENT);
    hp[2 * t + 0] = __halves2half2(__float2half_rn(x.x), __float2half_rn(x.y));
    hp[2 * t + 1] = __halves2half2(__float2half_rn(x.z), __float2half_rn(x.w));
}

// ============================ launch ============================================
static float* symf(const void* s) { void* p; cudaGetSymbolAddress(&p, s); return (float*)p; }
static __half* symh(const void* s) { void* p; cudaGetSymbolAddress(&p, s); return (__half*)p; }

extern "C" void kernel_launch(void* const* d_in, const int* in_sizes, int n_in,
                              void* d_out, int out_size)
{
    const float* feat     = (const float*)d_in[0];
    const float* key_bank = (const float*)d_in[1];
    const float* Wc1 = (const float*)d_in[2];  const float* bc1 = (const float*)d_in[3];
    const float* Wc2 = (const float*)d_in[4];  const float* bc2 = (const float*)d_in[5];
    const float* Wc3 = (const float*)d_in[6];  const float* bc3 = (const float*)d_in[7];
    const float* Wd1 = (const float*)d_in[8];  const float* bd1 = (const float*)d_in[9];
    const float* Wd2 = (const float*)d_in[10]; const float* bd2 = (const float*)d_in[11];
    const float* Wd3 = (const float*)d_in[12]; const float* bd3 = (const float*)d_in[13];
    const float* ln_w = (const float*)d_in[14];
    const float* ln_b = (const float*)d_in[15];
    const float* prelu_a = (const float*)d_in[16];
    const float* Wffn = (const float*)d_in[17];
    const float* bffn = (const float*)d_in[18];
    float* out = (float*)d_out;

    __half *feat_h = symh(&g_feat_h);
    __half *kb_h = symh(&g_kb_h);
    __half *W_h = symh(&g_W_h);
    __half *Q_h = symh(&g_Q_h);
    __half *K_h = symh(&g_K_h);
    __half *Vt_h = symh(&g_Vt_h);
    __half *E_h = symh(&g_E_h);
    __half *X_h = symh(&g_X_h);
    float *F = symf(&g_F), *RS = symf(&g_rsum);

    cudaFuncSetAttribute(gemm_proj,   cudaFuncAttributeMaxDynamicSharedMemorySize, SMEM_G);
    cudaFuncSetAttribute(gemm_f16<3>, cudaFuncAttributeMaxDynamicSharedMemorySize, SMEM_G);
    cudaFuncSetAttribute(gemm_f16<4>, cudaFuncAttributeMaxDynamicSharedMemorySize, SMEM_G);
    cudaFuncSetAttribute(gemm_f16<5>, cudaFuncAttributeMaxDynamicSharedMemorySize, SMEM_G);

    const dim3 blk(256);

    // ---- one conversion launch for inputs + all weights
    C9 c9;
    c9.src[0] = (const float4*)feat;     c9.dst[0] = (__half2*)feat_h; c9.n4[0] = (int)((size_t)N_ROIS * QDIM / 4);
    c9.src[1] = (const float4*)key_bank; c9.dst[1] = (__half2*)kb_h;   c9.n4[1] = (int)((size_t)N_BANK * DIM_IN / 4);
    const float* Ws[7] = { Wc1, Wd1, Wc2, Wd2, Wc3, Wd3, Wffn };
    for (int i = 0; i < 7; i++) {
        c9.src[2 + i] = (const float4*)Ws[i];
        c9.dst[2 + i] = (__half2*)(W_h + i * WSZ);
        c9.n4[2 + i]  = (int)(WSZ / 4);
    }
    conv9_kernel<<<1184, blk>>>(c9);
    zero_kernel<<<(2 * N_ROIS + 255) / 256, blk>>>(RS, 2 * N_ROIS);

    const size_t QO = (size_t)N_ROIS * LATENT;
    const size_t KO = (size_t)N_BANK * LATENT;
    const size_t VO = (size_t)LATENT * N_BANK;
    const size_t SO = (size_t)N_ROIS * N_BANK;

    // ---- fat projection launch: Q b0/b1, K b0/b1, Vt b0/b1 (1280 CTAs)
    GSegs gs;
    // Q: [4096,1024] = feat @ W^T, col-bias
    gs.s[0] = { feat_h, W_h + 0 * WSZ, Q_h,      QDIM, QDIM, LATENT, 4,    0, 0, bc1 };
    gs.s[1] = { feat_h, W_h + 1 * WSZ, Q_h + QO, QDIM, QDIM, LATENT, 4,  128, 0, bd1 };
    // K: [8192,1024], col-bias
    gs.s[2] = { kb_h, W_h + 2 * WSZ, K_h,      DIM_IN, DIM_IN, LATENT, 4,  256, 0, bc2 };
    gs.s[3] = { kb_h, W_h + 3 * WSZ, K_h + KO, DIM_IN, DIM_IN, LATENT, 4,  512, 0, bd2 };
    // Vt: [1024,8192] = W @ kb^T, row-bias
    gs.s[4] = { W_h + 4 * WSZ, kb_h, Vt_h,      DIM_IN, DIM_IN, N_BANK, 32,  768, 1, bc3 };
    gs.s[5] = { W_h + 5 * WSZ, kb_h, Vt_h + VO, DIM_IN, DIM_IN, N_BANK, 32, 1024, 1, bd3 };
    gemm_proj<<<1280, blk, SMEM_G>>>(gs);

    // ---- scores + exp fused, both branches
    gemm_f16<5><<<dim3(32, 32, 2), blk, SMEM_G>>>(Q_h, LATENT, QO,
        K_h, LATENT, KO, LATENT, nullptr, E_h, N_BANK, SO, 0.03125f, nullptr, RS, N_ROIS);

    // ---- PV, both branches
    gemm_f16<3><<<dim3(4, 32, 2), blk, SMEM_G>>>(E_h, N_BANK, SO,
        Vt_h, N_BANK, VO, N_BANK, F, nullptr, LATENT, QO, 0.f, nullptr, RS, N_ROIS);

    // ---- gate + LN + PReLU -> X
    gate_ln_kernel<<<N_ROIS, blk>>>(F, ln_w, ln_b, prelu_a, X_h);

    // ---- FFN (1-term)
    gemm_f16<4><<<dim3(8, 32, 1), blk, SMEM_G>>>(X_h, LATENT, 0,
        W_h + 6 * WSZ, LATENT, 0, LATENT, out, nullptr, DIM_IN, 0, 0.f, bffn, nullptr, 0);
}

// round 14
// speedup vs baseline: 2.0622x; 1.1636x over previous
#include <cuda_runtime.h>
#include <cuda_fp16.h>
#include <cstdint>
#include <math.h>

#define DIM_IN 2048
#define QDIM   2048
#define LATENT 1024
#define N_ROIS 4096
#define N_BANK 8192
#define LN_EPS 1e-5f

// ============================ static scratch ====================================
__device__ __half g_feat_h[(size_t)N_ROIS * QDIM];
__device__ __half g_kb_h[(size_t)N_BANK * DIM_IN];
#define WSZ ((size_t)LATENT * QDIM)
__device__ __half g_W_h[7 * WSZ];
__device__ __half g_Q_h[(size_t)2 * N_ROIS * LATENT];
__device__ __half g_K_h[(size_t)2 * N_BANK * LATENT];
__device__ __half g_Vt_h[(size_t)2 * LATENT * N_BANK];
__device__ __half g_E_h[(size_t)2 * N_ROIS * N_BANK];
__device__ float  g_F  [(size_t)2 * N_ROIS * LATENT];
__device__ __half g_X_h[(size_t)N_ROIS * LATENT];
__device__ float g_rsum[2 * N_ROIS];

// ============================ PTX helpers =======================================
__device__ __forceinline__ uint32_t smem_u32(const void* p) {
    uint32_t a;
    asm("{ .reg .u64 t; cvta.to.shared.u64 t, %1; cvt.u32.u64 %0, t; }" : "=r"(a) : "l"(p));
    return a;
}
__device__ __forceinline__ void cp_async16(uint32_t s, const void* g) {
    asm volatile("cp.async.cg.shared.global [%0], [%1], 16;\n" :: "r"(s), "l"(g));
}
#define CP_COMMIT() asm volatile("cp.async.commit_group;\n" ::: "memory")
#define CP_WAIT1()  asm volatile("cp.async.wait_group 1;\n" ::: "memory")

#define LDSM_X4(r, a)                                                               \
    asm volatile("ldmatrix.sync.aligned.m8n8.x4.shared.b16 {%0,%1,%2,%3}, [%4];"    \
        : "=r"((r)[0]), "=r"((r)[1]), "=r"((r)[2]), "=r"((r)[3]) : "r"(a))

#define MMA_F16(c, a, b0, b1)                                                       \
    asm volatile("mma.sync.aligned.m16n8k16.row.col.f32.f16.f16.f32 "               \
        "{%0,%1,%2,%3}, {%4,%5,%6,%7}, {%8,%9}, {%0,%1,%2,%3};"                     \
        : "+f"((c)[0]), "+f"((c)[1]), "+f"((c)[2]), "+f"((c)[3])                    \
        : "r"((a)[0]), "r"((a)[1]), "r"((a)[2]), "r"((a)[3]), "r"(b0), "r"(b1))

// ============================ common GEMM pieces ================================
// Block 128x256x64, 8 warps, warp tile 64x64, 3-stage cp.async, single-term fp16.
// smem rows padded to 144 B (128 B data + 16) -> conflict-free ldmatrix phases.
#define ROW_B    144
#define A_TILE_B (128 * ROW_B)            // 18432
#define B_TILE_B (256 * ROW_B)            // 36864
#define STAGE_B  (A_TILE_B + B_TILE_B)    // 55296
#define SMEM_G   (3 * STAGE_B)            // 165888

__device__ __forceinline__ void load_stage_g(uint32_t st,
    const __half* __restrict__ Ah, int lda, int m0,
    const __half* __restrict__ Bh, int ldb, int n0, int k0, int tid)
{
#pragma unroll
    for (int it = 0; it < 4; ++it) {           // A: 128 rows x 8 x16B
        int id = tid + it * 256;
        int r  = id >> 3;
        int cw = id & 7;
        cp_async16(st + (uint32_t)(r * ROW_B + cw * 16),
                   Ah + (size_t)(m0 + r) * lda + k0 + cw * 8);
    }
#pragma unroll
    for (int it = 0; it < 8; ++it) {           // B: 256 rows x 8 x16B
        int id = tid + it * 256;
        int r  = id >> 3;
        int cw = id & 7;
        cp_async16(st + A_TILE_B + (uint32_t)(r * ROW_B + cw * 16),
                   Bh + (size_t)(n0 + r) * ldb + k0 + cw * 8);
    }
}

// mainloop: batched LDSM per k16-step (4 A + 4 B up front), K-chunk 64.
__device__ __forceinline__ void gemm_mainloop(uint32_t sbase,
    const __half* __restrict__ Ah, int lda, int m0,
    const __half* __restrict__ Bh, int ldb, int n0, int K, int tid,
    uint32_t aoff, uint32_t boff, float acc[4][4][8])
{
    const int nc = K >> 6;
    load_stage_g(sbase, Ah, lda, m0, Bh, ldb, n0, 0, tid);
    CP_COMMIT();
    if (nc > 1) load_stage_g(sbase + STAGE_B, Ah, lda, m0, Bh, ldb, n0, 64, tid);
    CP_COMMIT();

#pragma unroll 1
    for (int c = 0; c < nc; c++) {
        CP_WAIT1();
        __syncthreads();
        int cn = c + 2;
        if (cn < nc)
            load_stage_g(sbase + (uint32_t)(cn % 3) * STAGE_B, Ah, lda, m0, Bh, ldb, n0, cn * 64, tid);
        CP_COMMIT();

        const uint32_t st  = sbase + (uint32_t)(c % 3) * STAGE_B;
        const uint32_t sAh = st, sBh = st + A_TILE_B;
#pragma unroll
        for (int ks = 0; ks < 4; ks++) {
            uint32_t ah[4][4], bh[4][4];
#pragma unroll
            for (int mi = 0; mi < 4; mi++)
                LDSM_X4(ah[mi], sAh + aoff + (uint32_t)(mi * (16 * ROW_B) + ks * 32));
#pragma unroll
            for (int p = 0; p < 4; p++)
                LDSM_X4(bh[p], sBh + boff + (uint32_t)(p * (16 * ROW_B) + ks * 32));
#pragma unroll
            for (int p = 0; p < 4; p++)
#pragma unroll
                for (int mi = 0; mi < 4; mi++) {
                    MMA_F16((acc[mi][p] + 0), ah[mi], bh[p][0], bh[p][1]);
                    MMA_F16((acc[mi][p] + 4), ah[mi], bh[p][2], bh[p][3]);
                }
        }
    }
}

// ============================ fat projection GEMM ===============================
struct GSeg {
    const __half* A; const __half* B; __half* C;
    int lda, ldb, ldc, nx, base, rowbias;
    const float* bias;
};
struct GSegs { GSeg s[6]; };

__global__ __launch_bounds__(256, 1)
void gemm_proj(GSegs segs)
{
    extern __shared__ __align__(16) char smem[];
    const uint32_t sbase = smem_u32(smem);
    const int tid = threadIdx.x, wid = tid >> 5, lane = tid & 31;
    const int bid = blockIdx.x;

    int si = 0;
#pragma unroll
    for (int i = 1; i < 6; i++) if (bid >= segs.s[i].base) si = i;
    const GSeg sg = segs.s[si];
    const int lid = bid - sg.base;
    const int m0 = (lid / sg.nx) * 128;
    const int n0 = (lid % sg.nx) * 256;
    const int wm = wid & 1, wn = wid >> 1;

    const uint32_t aoff = (uint32_t)((wm * 64 + (lane & 15)) * ROW_B + (lane >> 4) * 16);
    const uint32_t boff = (uint32_t)((wn * 64 + ((lane >> 4) & 1) * 8 + (lane & 7)) * ROW_B
                                     + ((lane >> 3) & 1) * 16);

    float acc[4][4][8];
#pragma unroll
    for (int i = 0; i < 4; i++)
#pragma unroll
        for (int j = 0; j < 4; j++)
#pragma unroll
            for (int q = 0; q < 8; q++) acc[i][j][q] = 0.f;

    gemm_mainloop(sbase, sg.A, sg.lda, m0, sg.B, sg.ldb, n0, QDIM, tid, aoff, boff, acc);

#pragma unroll
    for (int mi = 0; mi < 4; mi++) {
        const int r0 = m0 + wm * 64 + mi * 16 + (lane >> 2);
        const int r1 = r0 + 8;
        float rb0 = 0.f, rb1 = 0.f;
        if (sg.rowbias) { rb0 = sg.bias[r0]; rb1 = sg.bias[r1]; }
#pragma unroll
        for (int p = 0; p < 4; p++) {
#pragma unroll
            for (int n8 = 0; n8 < 2; n8++) {
                const int col = n0 + wn * 64 + p * 16 + n8 * 8 + 2 * (lane & 3);
                const float* a4 = acc[mi][p] + n8 * 4;
                float v0 = a4[0], v1 = a4[1], v2 = a4[2], v3 = a4[3];
                if (sg.rowbias) {
                    v0 += rb0; v1 += rb0; v2 += rb1; v3 += rb1;
                } else {
                    float b0 = sg.bias[col], b1 = sg.bias[col + 1];
                    v0 += b0; v1 += b1; v2 += b0; v3 += b1;
                }
                *reinterpret_cast<__half2*>(sg.C + (size_t)r0 * sg.ldc + col) =
                    __halves2half2(__float2half_rn(v0), __float2half_rn(v1));
                *reinterpret_cast<__half2*>(sg.C + (size_t)r1 * sg.ldc + col) =
                    __halves2half2(__float2half_rn(v2), __float2half_rn(v3));
            }
        }
    }
}

// ============================ templated GEMM (scores/PV/FFN) ====================
// MODE 3: f32 *1/rsum[row] | 4: f32 +col-bias
// MODE 5: e = exp(alpha*acc) -> fp16 out; atomicAdd row sums into rsum
template<int MODE>
__global__ __launch_bounds__(256, 1)
void gemm_f16(const __half* __restrict__ Ah, int lda, size_t zsA,
              const __half* __restrict__ Bh, int ldb, size_t zsB,
              int K,
              float* __restrict__ Cf, __half* __restrict__ Ch, int ldc, size_t zsC,
              float alpha, const float* __restrict__ bias,
              float* __restrict__ rsum, int zrs)
{
    extern __shared__ __align__(16) char smem[];
    const uint32_t sbase = smem_u32(smem);
    const int tid = threadIdx.x, wid = tid >> 5, lane = tid & 31;
    const int z = blockIdx.z;
    const int m0 = blockIdx.y * 128, n0 = blockIdx.x * 256;
    const int wm = wid & 1, wn = wid >> 1;

    Ah += (size_t)z * zsA;
    Bh += (size_t)z * zsB;
    if (Cf) Cf += (size_t)z * zsC;
    if (Ch) Ch += (size_t)z * zsC;
    if (rsum) rsum += (size_t)z * zrs;

    const uint32_t aoff = (uint32_t)((wm * 64 + (lane & 15)) * ROW_B + (lane >> 4) * 16);
    const uint32_t boff = (uint32_t)((wn * 64 + ((lane >> 4) & 1) * 8 + (lane & 7)) * ROW_B
                                     + ((lane >> 3) & 1) * 16);

    float acc[4][4][8];
#pragma unroll
    for (int i = 0; i < 4; i++)
#pragma unroll
        for (int j = 0; j < 4; j++)
#pragma unroll
            for (int q = 0; q < 8; q++) acc[i][j][q] = 0.f;

    gemm_mainloop(sbase, Ah, lda, m0, Bh, ldb, n0, K, tid, aoff, boff, acc);

#pragma unroll
    for (int mi = 0; mi < 4; mi++) {
        const int r0 = m0 + wm * 64 + mi * 16 + (lane >> 2);
        const int r1 = r0 + 8;
        float s0 = 1.f, s1 = 1.f;
        if (MODE == 3) { s0 = 1.f / rsum[r0]; s1 = 1.f / rsum[r1]; }
        float rsum0 = 0.f, rsum1 = 0.f;
#pragma unroll
        for (int p = 0; p < 4; p++) {
#pragma unroll
            for (int n8 = 0; n8 < 2; n8++) {
                const int col = n0 + wn * 64 + p * 16 + n8 * 8 + 2 * (lane & 3);
                const float* a4 = acc[mi][p] + n8 * 4;
                float v0 = a4[0], v1 = a4[1], v2 = a4[2], v3 = a4[3];
                if (MODE == 5) {
                    v0 = __expf(v0 * alpha); v1 = __expf(v1 * alpha);
                    v2 = __expf(v2 * alpha); v3 = __expf(v3 * alpha);
                    rsum0 += v0 + v1; rsum1 += v2 + v3;
                    *reinterpret_cast<__half2*>(Ch + (size_t)r0 * ldc + col) =
                        __halves2half2(__float2half_rn(v0), __float2half_rn(v1));
                    *reinterpret_cast<__half2*>(Ch + (size_t)r1 * ldc + col) =
                        __halves2half2(__float2half_rn(v2), __float2half_rn(v3));
                    continue;
                }
                if (MODE == 3) { v0 *= s0; v1 *= s0; v2 *= s1; v3 *= s1; }
                if (MODE == 4) {
                    float b0 = bias[col], b1 = bias[col + 1];
                    v0 += b0; v1 += b1; v2 += b0; v3 += b1;
                }
                *reinterpret_cast<float2*>(Cf + (size_t)r0 * ldc + col) = make_float2(v0, v1);
                *reinterpret_cast<float2*>(Cf + (size_t)r1 * ldc + col) = make_float2(v2, v3);
            }
        }
        if (MODE == 5) {
            rsum0 += __shfl_xor_sync(0xffffffffu, rsum0, 1);
            rsum0 += __shfl_xor_sync(0xffffffffu, rsum0, 2);
            rsum1 += __shfl_xor_sync(0xffffffffu, rsum1, 1);
            rsum1 += __shfl_xor_sync(0xffffffffu, rsum1, 2);
            if ((lane & 3) == 0) {
                atomicAdd(rsum + r0, rsum0);
                atomicAdd(rsum + r1, rsum1);
            }
        }
    }
}

// ============================ aux kernels =======================================
struct C9 { const float4* src[9]; __half2* dst[9]; int n4[9]; };
__global__ __launch_bounds__(256)
void conv9_kernel(C9 c)
{
#pragma unroll 1
    for (int s = 0; s < 9; s++) {
        const float4* sp = c.src[s];
        __half2* dp = c.dst[s];
        const int n = c.n4[s];
        for (int i = blockIdx.x * blockDim.x + threadIdx.x; i < n; i += gridDim.x * blockDim.x) {
            float4 v = sp[i];
            dp[2 * i + 0] = __halves2half2(__float2half_rn(v.x), __float2half_rn(v.y));
            dp[2 * i + 1] = __halves2half2(__float2half_rn(v.z), __float2half_rn(v.w));
        }
    }
}

__global__ __launch_bounds__(256)
void zero_kernel(float* __restrict__ p, int n)
{
    int i = blockIdx.x * blockDim.x + threadIdx.x;
    if (i < n) p[i] = 0.f;
}

__global__ __launch_bounds__(256)
void gate_ln_kernel(const float* __restrict__ F,
                    const float* __restrict__ ln_w, const float* __restrict__ ln_b,
                    const float* __restrict__ prelu_a,
                    __half* __restrict__ Xh)
{
    const int row = blockIdx.x;
    const int t = threadIdx.x, lane = t & 31, w = t >> 5;
    const float4 f1 = reinterpret_cast<const float4*>(F + (size_t)row * LATENT)[t];
    const float4 f2 = reinterpret_cast<const float4*>(F + (size_t)(N_ROIS + row) * LATENT)[t];
    float4 c;
    c.x = f1.x * f2.x; c.y = f1.y * f2.y; c.z = f1.z * f2.z; c.w = f1.w * f2.w;

    __shared__ float red[8], mu_sh, var_sh;
    float s = c.x + c.y + c.z + c.w;
#pragma unroll
    for (int off = 16; off > 0; off >>= 1) s += __shfl_xor_sync(0xffffffffu, s, off);
    if (lane == 0) red[w] = s;
    __syncthreads();
    if (t == 0) {
        float ss = 0.f;
#pragma unroll
        for (int i = 0; i < 8; i++) ss += red[i];
        mu_sh = ss * (1.f / LATENT);
    }
    __syncthreads();
    const float mu = mu_sh;
    float dx = c.x - mu, dy = c.y - mu, dz = c.z - mu, dw = c.w - mu;
    float sq = dx * dx + dy * dy + dz * dz + dw * dw;
#pragma unroll
    for (int off = 16; off > 0; off >>= 1) sq += __shfl_xor_sync(0xffffffffu, sq, off);
    __syncthreads();
    if (lane == 0) red[w] = sq;
    __syncthreads();
    if (t == 0) {
        float ss = 0.f;
#pragma unroll
        for (int i = 0; i < 8; i++) ss += red[i];
        var_sh = ss * (1.f / LATENT);
    }
    __syncthreads();
    const float inv = rsqrtf(var_sh + LN_EPS);
    const float slope = prelu_a[0];
    const float4 wv = reinterpret_cast<const float4*>(ln_w)[t];
    const float4 bv = reinterpret_cast<const float4*>(ln_b)[t];
    float4 x;
    x.x = dx * inv * wv.x + bv.x;  x.y = dy * inv * wv.y + bv.y;
    x.z = dz * inv * wv.z + bv.z;  x.w = dw * inv * wv.w + bv.w;
    x.x = x.x >= 0.f ? x.x : slope * x.x;
    x.y = x.y >= 0.f ? x.y : slope * x.y;
    x.z = x.z >= 0.f ? x.z : slope * x.z;
    x.w = x.w >= 0.f ? x.w : slope * x.w;

    __half2* hp = reinterpret_cast<__half2*>(Xh + (size_t)row * LATENT);
    hp[2 * t + 0] = __halves2half2(__float2half_rn(x.x), __float2half_rn(x.y));
    hp[2 * t + 1] = __halves2half2(__float2half_rn(x.z), __float2half_rn(x.w));
}

// ============================ launch ============================================
static float* symf(const void* s) { void* p; cudaGetSymbolAddress(&p, s); return (float*)p; }
static __half* symh(const void* s) { void* p; cudaGetSymbolAddress(&p, s); return (__half*)p; }

extern "C" void kernel_launch(void* const* d_in, const int* in_sizes, int n_in,
                              void* d_out, int out_size)
{
    const float* feat     = (const float*)d_in[0];
    const float* key_bank = (const float*)d_in[1];
    const float* Wc1 = (const float*)d_in[2];  const float* bc1 = (const float*)d_in[3];
    const float* Wc2 = (const float*)d_in[4];  const float* bc2 = (const float*)d_in[5];
    const float* Wc3 = (const float*)d_in[6];  const float* bc3 = (const float*)d_in[7];
    const float* Wd1 = (const float*)d_in[8];  const float* bd1 = (const float*)d_in[9];
    const float* Wd2 = (const float*)d_in[10]; const float* bd2 = (const float*)d_in[11];
    const float* Wd3 = (const float*)d_in[12]; const float* bd3 = (const float*)d_in[13];
    const float* ln_w = (const float*)d_in[14];
    const float* ln_b = (const float*)d_in[15];
    const float* prelu_a = (const float*)d_in[16];
    const float* Wffn = (const float*)d_in[17];
    const float* bffn = (const float*)d_in[18];
    float* out = (float*)d_out;

    __half *feat_h = symh(&g_feat_h);
    __half *kb_h = symh(&g_kb_h);
    __half *W_h = symh(&g_W_h);
    __half *Q_h = symh(&g_Q_h);
    __half *K_h = symh(&g_K_h);
    __half *Vt_h = symh(&g_Vt_h);
    __half *E_h = symh(&g_E_h);
    __half *X_h = symh(&g_X_h);
    float *F = symf(&g_F), *RS = symf(&g_rsum);

    cudaFuncSetAttribute(gemm_proj,   cudaFuncAttributeMaxDynamicSharedMemorySize, SMEM_G);
    cudaFuncSetAttribute(gemm_f16<3>, cudaFuncAttributeMaxDynamicSharedMemorySize, SMEM_G);
    cudaFuncSetAttribute(gemm_f16<4>, cudaFuncAttributeMaxDynamicSharedMemorySize, SMEM_G);
    cudaFuncSetAttribute(gemm_f16<5>, cudaFuncAttributeMaxDynamicSharedMemorySize, SMEM_G);

    const dim3 blk(256);

    // ---- one conversion launch for inputs + all weights
    C9 c9;
    c9.src[0] = (const float4*)feat;     c9.dst[0] = (__half2*)feat_h; c9.n4[0] = (int)((size_t)N_ROIS * QDIM / 4);
    c9.src[1] = (const float4*)key_bank; c9.dst[1] = (__half2*)kb_h;   c9.n4[1] = (int)((size_t)N_BANK * DIM_IN / 4);
    const float* Ws[7] = { Wc1, Wd1, Wc2, Wd2, Wc3, Wd3, Wffn };
    for (int i = 0; i < 7; i++) {
        c9.src[2 + i] = (const float4*)Ws[i];
        c9.dst[2 + i] = (__half2*)(W_h + i * WSZ);
        c9.n4[2 + i]  = (int)(WSZ / 4);
    }
    conv9_kernel<<<1184, blk>>>(c9);
    zero_kernel<<<(2 * N_ROIS + 255) / 256, blk>>>(RS, 2 * N_ROIS);

    const size_t QO = (size_t)N_ROIS * LATENT;
    const size_t KO = (size_t)N_BANK * LATENT;
    const size_t VO = (size_t)LATENT * N_BANK;
    const size_t SO = (size_t)N_ROIS * N_BANK;

    // ---- fat projection launch: Q b0/b1, K b0/b1, Vt b0/b1 (1280 CTAs)
    GSegs gs;
    gs.s[0] = { feat_h, W_h + 0 * WSZ, Q_h,      QDIM, QDIM, LATENT, 4,    0, 0, bc1 };
    gs.s[1] = { feat_h, W_h + 1 * WSZ, Q_h + QO, QDIM, QDIM, LATENT, 4,  128, 0, bd1 };
    gs.s[2] = { kb_h, W_h + 2 * WSZ, K_h,      DIM_IN, DIM_IN, LATENT, 4,  256, 0, bc2 };
    gs.s[3] = { kb_h, W_h + 3 * WSZ, K_h + KO, DIM_IN, DIM_IN, LATENT, 4,  512, 0, bd2 };
    gs.s[4] = { W_h + 4 * WSZ, kb_h, Vt_h,      DIM_IN, DIM_IN, N_BANK, 32,  768, 1, bc3 };
    gs.s[5] = { W_h + 5 * WSZ, kb_h, Vt_h + VO, DIM_IN, DIM_IN, N_BANK, 32, 1024, 1, bd3 };
    gemm_proj<<<1280, blk, SMEM_G>>>(gs);

    // ---- scores + exp fused, both branches
    gemm_f16<5><<<dim3(32, 32, 2), blk, SMEM_G>>>(Q_h, LATENT, QO,
        K_h, LATENT, KO, LATENT, nullptr, E_h, N_BANK, SO, 0.03125f, nullptr, RS, N_ROIS);

    // ---- PV, both branches
    gemm_f16<3><<<dim3(4, 32, 2), blk, SMEM_G>>>(E_h, N_BANK, SO,
        Vt_h, N_BANK, VO, N_BANK, F, nullptr, LATENT, QO, 0.f, nullptr, RS, N_ROIS);

    // ---- gate + LN + PReLU -> X
    gate_ln_kernel<<<N_ROIS, blk>>>(F, ln_w, ln_b, prelu_a, X_h);

    // ---- FFN (1-term)
    gemm_f16<4><<<dim3(8, 32, 1), blk, SMEM_G>>>(X_h, LATENT, 0,
        W_h + 6 * WSZ, LATENT, 0, LATENT, out, nullptr, DIM_IN, 0, 0.f, bffn, nullptr, 0);
}

// round 15
// speedup vs baseline: 2.1779x; 1.0561x over previous
#include <cuda_runtime.h>
#include <cuda_fp16.h>
#include <cstdint>
#include <math.h>

#define DIM_IN 2048
#define QDIM   2048
#define LATENT 1024
#define N_ROIS 4096
#define N_BANK 8192
#define LN_EPS 1e-5f

// ============================ static scratch ====================================
__device__ __half g_feat_h[(size_t)N_ROIS * QDIM];
__device__ __half g_kb_h[(size_t)N_BANK * DIM_IN];
#define WSZ ((size_t)LATENT * QDIM)
__device__ __half g_W_h[7 * WSZ];
__device__ __half g_Q_h[(size_t)2 * N_ROIS * LATENT];
__device__ __half g_K_h[(size_t)2 * N_BANK * LATENT];
__device__ __half g_Vt_h[(size_t)2 * LATENT * N_BANK];
__device__ __half g_E_h[(size_t)2 * N_ROIS * N_BANK];
__device__ float  g_F  [(size_t)2 * N_ROIS * LATENT];
__device__ __half g_X_h[(size_t)N_ROIS * LATENT];
__device__ float g_rsum[2 * N_ROIS];

// ============================ PTX helpers =======================================
__device__ __forceinline__ uint32_t smem_u32(const void* p) {
    uint32_t a;
    asm("{ .reg .u64 t; cvta.to.shared.u64 t, %1; cvt.u32.u64 %0, t; }" : "=r"(a) : "l"(p));
    return a;
}
__device__ __forceinline__ void cp_async16(uint32_t s, const void* g) {
    asm volatile("cp.async.cg.shared.global [%0], [%1], 16;\n" :: "r"(s), "l"(g));
}
#define CP_COMMIT() asm volatile("cp.async.commit_group;\n" ::: "memory")
#define CP_WAIT1()  asm volatile("cp.async.wait_group 1;\n" ::: "memory")

#define LDSM_X4(r, a)                                                               \
    asm volatile("ldmatrix.sync.aligned.m8n8.x4.shared.b16 {%0,%1,%2,%3}, [%4];"    \
        : "=r"((r)[0]), "=r"((r)[1]), "=r"((r)[2]), "=r"((r)[3]) : "r"(a))

#define MMA_F16(c, a, b0, b1)                                                       \
    asm volatile("mma.sync.aligned.m16n8k16.row.col.f32.f16.f16.f32 "               \
        "{%0,%1,%2,%3}, {%4,%5,%6,%7}, {%8,%9}, {%0,%1,%2,%3};"                     \
        : "+f"((c)[0]), "+f"((c)[1]), "+f"((c)[2]), "+f"((c)[3])                    \
        : "r"((a)[0]), "r"((a)[1]), "r"((a)[2]), "r"((a)[3]), "r"(b0), "r"(b1))

// ============================ common GEMM pieces ================================
// Block 128x256x64, 16 warps (512 thr), warp tile 32x64 (4M x 4N warp grid),
// 3-stage cp.async, single-term fp16. smem rows padded to 144 B.
#define ROW_B    144
#define A_TILE_B (128 * ROW_B)            // 18432
#define B_TILE_B (256 * ROW_B)            // 36864
#define STAGE_B  (A_TILE_B + B_TILE_B)    // 55296
#define SMEM_G   (3 * STAGE_B)            // 165888

__device__ __forceinline__ void load_stage_g(uint32_t st,
    const __half* __restrict__ Ah, int lda, int m0,
    const __half* __restrict__ Bh, int ldb, int n0, int k0, int tid)
{
#pragma unroll
    for (int it = 0; it < 2; ++it) {           // A: 128 rows x 8 x16B (1024 tasks)
        int id = tid + it * 512;
        int r  = id >> 3;
        int cw = id & 7;
        cp_async16(st + (uint32_t)(r * ROW_B + cw * 16),
                   Ah + (size_t)(m0 + r) * lda + k0 + cw * 8);
    }
#pragma unroll
    for (int it = 0; it < 4; ++it) {           // B: 256 rows x 8 x16B (2048 tasks)
        int id = tid + it * 512;
        int r  = id >> 3;
        int cw = id & 7;
        cp_async16(st + A_TILE_B + (uint32_t)(r * ROW_B + cw * 16),
                   Bh + (size_t)(n0 + r) * ldb + k0 + cw * 8);
    }
}

// mainloop: batched LDSM per k16-step (2 A + 4 B), K-chunk 64.
__device__ __forceinline__ void gemm_mainloop(uint32_t sbase,
    const __half* __restrict__ Ah, int lda, int m0,
    const __half* __restrict__ Bh, int ldb, int n0, int K, int tid,
    uint32_t aoff, uint32_t boff, float acc[2][4][8])
{
    const int nc = K >> 6;
    load_stage_g(sbase, Ah, lda, m0, Bh, ldb, n0, 0, tid);
    CP_COMMIT();
    if (nc > 1) load_stage_g(sbase + STAGE_B, Ah, lda, m0, Bh, ldb, n0, 64, tid);
    CP_COMMIT();

#pragma unroll 1
    for (int c = 0; c < nc; c++) {
        CP_WAIT1();
        __syncthreads();
        int cn = c + 2;
        if (cn < nc)
            load_stage_g(sbase + (uint32_t)(cn % 3) * STAGE_B, Ah, lda, m0, Bh, ldb, n0, cn * 64, tid);
        CP_COMMIT();

        const uint32_t st  = sbase + (uint32_t)(c % 3) * STAGE_B;
        const uint32_t sAh = st, sBh = st + A_TILE_B;
#pragma unroll
        for (int ks = 0; ks < 4; ks++) {
            uint32_t ah[2][4], bh[4][4];
#pragma unroll
            for (int mi = 0; mi < 2; mi++)
                LDSM_X4(ah[mi], sAh + aoff + (uint32_t)(mi * (16 * ROW_B) + ks * 32));
#pragma unroll
            for (int p = 0; p < 4; p++)
                LDSM_X4(bh[p], sBh + boff + (uint32_t)(p * (16 * ROW_B) + ks * 32));
#pragma unroll
            for (int p = 0; p < 4; p++)
#pragma unroll
                for (int mi = 0; mi < 2; mi++) {
                    MMA_F16((acc[mi][p] + 0), ah[mi], bh[p][0], bh[p][1]);
                    MMA_F16((acc[mi][p] + 4), ah[mi], bh[p][2], bh[p][3]);
                }
        }
    }
}

// ============================ fat projection GEMM ===============================
struct GSeg {
    const __half* A; const __half* B; __half* C;
    int lda, ldb, ldc, nx, base, rowbias;
    const float* bias;
};
struct GSegs { GSeg s[6]; };

__global__ __launch_bounds__(512, 1)
void gemm_proj(GSegs segs)
{
    extern __shared__ __align__(16) char smem[];
    const uint32_t sbase = smem_u32(smem);
    const int tid = threadIdx.x, wid = tid >> 5, lane = tid & 31;
    const int bid = blockIdx.x;

    int si = 0;
#pragma unroll
    for (int i = 1; i < 6; i++) if (bid >= segs.s[i].base) si = i;
    const GSeg sg = segs.s[si];
    const int lid = bid - sg.base;
    const int m0 = (lid / sg.nx) * 128;
    const int n0 = (lid % sg.nx) * 256;
    const int wm = wid & 3, wn = wid >> 2;

    const uint32_t aoff = (uint32_t)((wm * 32 + (lane & 15)) * ROW_B + (lane >> 4) * 16);
    const uint32_t boff = (uint32_t)((wn * 64 + ((lane >> 4) & 1) * 8 + (lane & 7)) * ROW_B
                                     + ((lane >> 3) & 1) * 16);

    float acc[2][4][8];
#pragma unroll
    for (int i = 0; i < 2; i++)
#pragma unroll
        for (int j = 0; j < 4; j++)
#pragma unroll
            for (int q = 0; q < 8; q++) acc[i][j][q] = 0.f;

    gemm_mainloop(sbase, sg.A, sg.lda, m0, sg.B, sg.ldb, n0, QDIM, tid, aoff, boff, acc);

#pragma unroll
    for (int mi = 0; mi < 2; mi++) {
        const int r0 = m0 + wm * 32 + mi * 16 + (lane >> 2);
        const int r1 = r0 + 8;
        float rb0 = 0.f, rb1 = 0.f;
        if (sg.rowbias) { rb0 = sg.bias[r0]; rb1 = sg.bias[r1]; }
#pragma unroll
        for (int p = 0; p < 4; p++) {
#pragma unroll
            for (int n8 = 0; n8 < 2; n8++) {
                const int col = n0 + wn * 64 + p * 16 + n8 * 8 + 2 * (lane & 3);
                const float* a4 = acc[mi][p] + n8 * 4;
                float v0 = a4[0], v1 = a4[1], v2 = a4[2], v3 = a4[3];
                if (sg.rowbias) {
                    v0 += rb0; v1 += rb0; v2 += rb1; v3 += rb1;
                } else {
                    float b0 = sg.bias[col], b1 = sg.bias[col + 1];
                    v0 += b0; v1 += b1; v2 += b0; v3 += b1;
                }
                *reinterpret_cast<__half2*>(sg.C + (size_t)r0 * sg.ldc + col) =
                    __halves2half2(__float2half_rn(v0), __float2half_rn(v1));
                *reinterpret_cast<__half2*>(sg.C + (size_t)r1 * sg.ldc + col) =
                    __halves2half2(__float2half_rn(v2), __float2half_rn(v3));
            }
        }
    }
}

// ============================ templated GEMM (scores/PV/FFN) ====================
// MODE 3: f32 *1/rsum[row] | 4: f32 +col-bias
// MODE 5: e = exp(alpha*acc) -> fp16 out; atomicAdd row sums into rsum
template<int MODE>
__global__ __launch_bounds__(512, 1)
void gemm_f16(const __half* __restrict__ Ah, int lda, size_t zsA,
              const __half* __restrict__ Bh, int ldb, size_t zsB,
              int K,
              float* __restrict__ Cf, __half* __restrict__ Ch, int ldc, size_t zsC,
              float alpha, const float* __restrict__ bias,
              float* __restrict__ rsum, int zrs)
{
    extern __shared__ __align__(16) char smem[];
    const uint32_t sbase = smem_u32(smem);
    const int tid = threadIdx.x, wid = tid >> 5, lane = tid & 31;
    const int z = blockIdx.z;
    const int m0 = blockIdx.y * 128, n0 = blockIdx.x * 256;
    const int wm = wid & 3, wn = wid >> 2;

    Ah += (size_t)z * zsA;
    Bh += (size_t)z * zsB;
    if (Cf) Cf += (size_t)z * zsC;
    if (Ch) Ch += (size_t)z * zsC;
    if (rsum) rsum += (size_t)z * zrs;

    const uint32_t aoff = (uint32_t)((wm * 32 + (lane & 15)) * ROW_B + (lane >> 4) * 16);
    const uint32_t boff = (uint32_t)((wn * 64 + ((lane >> 4) & 1) * 8 + (lane & 7)) * ROW_B
                                     + ((lane >> 3) & 1) * 16);

    float acc[2][4][8];
#pragma unroll
    for (int i = 0; i < 2; i++)
#pragma unroll
        for (int j = 0; j < 4; j++)
#pragma unroll
            for (int q = 0; q < 8; q++) acc[i][j][q] = 0.f;

    gemm_mainloop(sbase, Ah, lda, m0, Bh, ldb, n0, K, tid, aoff, boff, acc);

#pragma unroll
    for (int mi = 0; mi < 2; mi++) {
        const int r0 = m0 + wm * 32 + mi * 16 + (lane >> 2);
        const int r1 = r0 + 8;
        float s0 = 1.f, s1 = 1.f;
        if (MODE == 3) { s0 = 1.f / rsum[r0]; s1 = 1.f / rsum[r1]; }
        float rsum0 = 0.f, rsum1 = 0.f;
#pragma unroll
        for (int p = 0; p < 4; p++) {
#pragma unroll
            for (int n8 = 0; n8 < 2; n8++) {
                const int col = n0 + wn * 64 + p * 16 + n8 * 8 + 2 * (lane & 3);
                const float* a4 = acc[mi][p] + n8 * 4;
                float v0 = a4[0], v1 = a4[1], v2 = a4[2], v3 = a4[3];
                if (MODE == 5) {
                    v0 = __expf(v0 * alpha); v1 = __expf(v1 * alpha);
                    v2 = __expf(v2 * alpha); v3 = __expf(v3 * alpha);
                    rsum0 += v0 + v1; rsum1 += v2 + v3;
                    *reinterpret_cast<__half2*>(Ch + (size_t)r0 * ldc + col) =
                        __halves2half2(__float2half_rn(v0), __float2half_rn(v1));
                    *reinterpret_cast<__half2*>(Ch + (size_t)r1 * ldc + col) =
                        __halves2half2(__float2half_rn(v2), __float2half_rn(v3));
                    continue;
                }
                if (MODE == 3) { v0 *= s0; v1 *= s0; v2 *= s1; v3 *= s1; }
                if (MODE == 4) {
                    float b0 = bias[col], b1 = bias[col + 1];
                    v0 += b0; v1 += b1; v2 += b0; v3 += b1;
                }
                *reinterpret_cast<float2*>(Cf + (size_t)r0 * ldc + col) = make_float2(v0, v1);
                *reinterpret_cast<float2*>(Cf + (size_t)r1 * ldc + col) = make_float2(v2, v3);
            }
        }
        if (MODE == 5) {
            rsum0 += __shfl_xor_sync(0xffffffffu, rsum0, 1);
            rsum0 += __shfl_xor_sync(0xffffffffu, rsum0, 2);
            rsum1 += __shfl_xor_sync(0xffffffffu, rsum1, 1);
            rsum1 += __shfl_xor_sync(0xffffffffu, rsum1, 2);
            if ((lane & 3) == 0) {
                atomicAdd(rsum + r0, rsum0);
                atomicAdd(rsum + r1, rsum1);
            }
        }
    }
}

// ============================ aux kernels =======================================
struct C9 { const float4* src[9]; __half2* dst[9]; int n4[9]; };
__global__ __launch_bounds__(256)
void conv9_kernel(C9 c)
{
#pragma unroll 1
    for (int s = 0; s < 9; s++) {
        const float4* sp = c.src[s];
        __half2* dp = c.dst[s];
        const int n = c.n4[s];
        for (int i = blockIdx.x * blockDim.x + threadIdx.x; i < n; i += gridDim.x * blockDim.x) {
            float4 v = sp[i];
            dp[2 * i + 0] = __halves2half2(__float2half_rn(v.x), __float2half_rn(v.y));
            dp[2 * i + 1] = __halves2half2(__float2half_rn(v.z), __float2half_rn(v.w));
        }
    }
}

__global__ __launch_bounds__(256)
void zero_kernel(float* __restrict__ p, int n)
{
    int i = blockIdx.x * blockDim.x + threadIdx.x;
    if (i < n) p[i] = 0.f;
}

__global__ __launch_bounds__(256)
void gate_ln_kernel(const float* __restrict__ F,
                    const float* __restrict__ ln_w, const float* __restrict__ ln_b,
                    const float* __restrict__ prelu_a,
                    __half* __restrict__ Xh)
{
    const int row = blockIdx.x;
    const int t = threadIdx.x, lane = t & 31, w = t >> 5;
    const float4 f1 = reinterpret_cast<const float4*>(F + (size_t)row * LATENT)[t];
    const float4 f2 = reinterpret_cast<const float4*>(F + (size_t)(N_ROIS + row) * LATENT)[t];
    float4 c;
    c.x = f1.x * f2.x; c.y = f1.y * f2.y; c.z = f1.z * f2.z; c.w = f1.w * f2.w;

    __shared__ float red[8], mu_sh, var_sh;
    float s = c.x + c.y + c.z + c.w;
#pragma unroll
    for (int off = 16; off > 0; off >>= 1) s += __shfl_xor_sync(0xffffffffu, s, off);
    if (lane == 0) red[w] = s;
    __syncthreads();
    if (t == 0) {
        float ss = 0.f;
#pragma unroll
        for (int i = 0; i < 8; i++) ss += red[i];
        mu_sh = ss * (1.f / LATENT);
    }
    __syncthreads();
    const float mu = mu_sh;
    float dx = c.x - mu, dy = c.y - mu, dz = c.z - mu, dw = c.w - mu;
    float sq = dx * dx + dy * dy + dz * dz + dw * dw;
#pragma unroll
    for (int off = 16; off > 0; off >>= 1) sq += __shfl_xor_sync(0xffffffffu, sq, off);
    __syncthreads();
    if (lane == 0) red[w] = sq;
    __syncthreads();
    if (t == 0) {
        float ss = 0.f;
#pragma unroll
        for (int i = 0; i < 8; i++) ss += red[i];
        var_sh = ss * (1.f / LATENT);
    }
    __syncthreads();
    const float inv = rsqrtf(var_sh + LN_EPS);
    const float slope = prelu_a[0];
    const float4 wv = reinterpret_cast<const float4*>(ln_w)[t];
    const float4 bv = reinterpret_cast<const float4*>(ln_b)[t];
    float4 x;
    x.x = dx * inv * wv.x + bv.x;  x.y = dy * inv * wv.y + bv.y;
    x.z = dz * inv * wv.z + bv.z;  x.w = dw * inv * wv.w + bv.w;
    x.x = x.x >= 0.f ? x.x : slope * x.x;
    x.y = x.y >= 0.f ? x.y : slope * x.y;
    x.z = x.z >= 0.f ? x.z : slope * x.z;
    x.w = x.w >= 0.f ? x.w : slope * x.w;

    __half2* hp = reinterpret_cast<__half2*>(Xh + (size_t)row * LATENT);
    hp[2 * t + 0] = __halves2half2(__float2half_rn(x.x), __float2half_rn(x.y));
    hp[2 * t + 1] = __halves2half2(__float2half_rn(x.z), __float2half_rn(x.w));
}

// ============================ launch ============================================
static float* symf(const void* s) { void* p; cudaGetSymbolAddress(&p, s); return (float*)p; }
static __half* symh(const void* s) { void* p; cudaGetSymbolAddress(&p, s); return (__half*)p; }

extern "C" void kernel_launch(void* const* d_in, const int* in_sizes, int n_in,
                              void* d_out, int out_size)
{
    const float* feat     = (const float*)d_in[0];
    const float* key_bank = (const float*)d_in[1];
    const float* Wc1 = (const float*)d_in[2];  const float* bc1 = (const float*)d_in[3];
    const float* Wc2 = (const float*)d_in[4];  const float* bc2 = (const float*)d_in[5];
    const float* Wc3 = (const float*)d_in[6];  const float* bc3 = (const float*)d_in[7];
    const float* Wd1 = (const float*)d_in[8];  const float* bd1 = (const float*)d_in[9];
    const float* Wd2 = (const float*)d_in[10]; const float* bd2 = (const float*)d_in[11];
    const float* Wd3 = (const float*)d_in[12]; const float* bd3 = (const float*)d_in[13];
    const float* ln_w = (const float*)d_in[14];
    const float* ln_b = (const float*)d_in[15];
    const float* prelu_a = (const float*)d_in[16];
    const float* Wffn = (const float*)d_in[17];
    const float* bffn = (const float*)d_in[18];
    float* out = (float*)d_out;

    __half *feat_h = symh(&g_feat_h);
    __half *kb_h = symh(&g_kb_h);
    __half *W_h = symh(&g_W_h);
    __half *Q_h = symh(&g_Q_h);
    __half *K_h = symh(&g_K_h);
    __half *Vt_h = symh(&g_Vt_h);
    __half *E_h = symh(&g_E_h);
    __half *X_h = symh(&g_X_h);
    float *F = symf(&g_F), *RS = symf(&g_rsum);

    cudaFuncSetAttribute(gemm_proj,   cudaFuncAttributeMaxDynamicSharedMemorySize, SMEM_G);
    cudaFuncSetAttribute(gemm_f16<3>, cudaFuncAttributeMaxDynamicSharedMemorySize, SMEM_G);
    cudaFuncSetAttribute(gemm_f16<4>, cudaFuncAttributeMaxDynamicSharedMemorySize, SMEM_G);
    cudaFuncSetAttribute(gemm_f16<5>, cudaFuncAttributeMaxDynamicSharedMemorySize, SMEM_G);

    const dim3 blk(256);
    const dim3 blkG(512);

    // ---- one conversion launch for inputs + all weights
    C9 c9;
    c9.src[0] = (const float4*)feat;     c9.dst[0] = (__half2*)feat_h; c9.n4[0] = (int)((size_t)N_ROIS * QDIM / 4);
    c9.src[1] = (const float4*)key_bank; c9.dst[1] = (__half2*)kb_h;   c9.n4[1] = (int)((size_t)N_BANK * DIM_IN / 4);
    const float* Ws[7] = { Wc1, Wd1, Wc2, Wd2, Wc3, Wd3, Wffn };
    for (int i = 0; i < 7; i++) {
        c9.src[2 + i] = (const float4*)Ws[i];
        c9.dst[2 + i] = (__half2*)(W_h + i * WSZ);
        c9.n4[2 + i]  = (int)(WSZ / 4);
    }
    conv9_kernel<<<1184, blk>>>(c9);
    zero_kernel<<<(2 * N_ROIS + 255) / 256, blk>>>(RS, 2 * N_ROIS);

    const size_t QO = (size_t)N_ROIS * LATENT;
    const size_t KO = (size_t)N_BANK * LATENT;
    const size_t VO = (size_t)LATENT * N_BANK;
    const size_t SO = (size_t)N_ROIS * N_BANK;

    // ---- fat projection launch: Q b0/b1, K b0/b1, Vt b0/b1 (1280 CTAs)
    GSegs gs;
    gs.s[0] = { feat_h, W_h + 0 * WSZ, Q_h,      QDIM, QDIM, LATENT, 4,    0, 0, bc1 };
    gs.s[1] = { feat_h, W_h + 1 * WSZ, Q_h + QO, QDIM, QDIM, LATENT, 4,  128, 0, bd1 };
    gs.s[2] = { kb_h, W_h + 2 * WSZ, K_h,      DIM_IN, DIM_IN, LATENT, 4,  256, 0, bc2 };
    gs.s[3] = { kb_h, W_h + 3 * WSZ, K_h + KO, DIM_IN, DIM_IN, LATENT, 4,  512, 0, bd2 };
    gs.s[4] = { W_h + 4 * WSZ, kb_h, Vt_h,      DIM_IN, DIM_IN, N_BANK, 32,  768, 1, bc3 };
    gs.s[5] = { W_h + 5 * WSZ, kb_h, Vt_h + VO, DIM_IN, DIM_IN, N_BANK, 32, 1024, 1, bd3 };
    gemm_proj<<<1280, blkG, SMEM_G>>>(gs);

    // ---- scores + exp fused, both branches
    gemm_f16<5><<<dim3(32, 32, 2), blkG, SMEM_G>>>(Q_h, LATENT, QO,
        K_h, LATENT, KO, LATENT, nullptr, E_h, N_BANK, SO, 0.03125f, nullptr, RS, N_ROIS);

    // ---- PV, both branches
    gemm_f16<3><<<dim3(4, 32, 2), blkG, SMEM_G>>>(E_h, N_BANK, SO,
        Vt_h, N_BANK, VO, N_BANK, F, nullptr, LATENT, QO, 0.f, nullptr, RS, N_ROIS);

    // ---- gate + LN + PReLU -> X
    gate_ln_kernel<<<N_ROIS, blk>>>(F, ln_w, ln_b, prelu_a, X_h);

    // ---- FFN (1-term)
    gemm_f16<4><<<dim3(8, 32, 1), blkG, SMEM_G>>>(X_h, LATENT, 0,
        W_h + 6 * WSZ, LATENT, 0, LATENT, out, nullptr, DIM_IN, 0, 0.f, bffn, nullptr, 0);
}